// round 2
// baseline (speedup 1.0000x reference)
#include <cuda_runtime.h>
#include <cuda_bf16.h>
#include <math.h>

// Problem constants
#define BB 2
#define TT 2048
#define DM 2048
#define NH 32
#define NKV 8
#define HD 64
#define MROWS (BB*TT)          // 4096

// Scratch (device globals — no allocation allowed)
__device__ float g_q[MROWS * NH * HD];     // 32 MB
__device__ float g_k[MROWS * NKV * HD];    // 8 MB
__device__ float g_v[MROWS * NKV * HD];    // 8 MB
__device__ float g_att[MROWS * NH * HD];   // 32 MB

// ---------------------------------------------------------------------------
// SGEMM (NT): C[M,N] = A[M,K] * B[N,K]^T  (both operands K-contiguous)
// 128x128 block tile, BK=16, 256 threads, 8x8 per-thread tile.
// ---------------------------------------------------------------------------
#define GBM 128
#define GBN 128
#define GBK 16

__global__ __launch_bounds__(256) void gemm_nt(
    const float* __restrict__ A, const float* __restrict__ B,
    float* __restrict__ C, int M, int N, int K)
{
    __shared__ float As[GBK][GBM];
    __shared__ float Bs[GBK][GBN];

    const int tid  = threadIdx.x;
    const int brow = blockIdx.y * GBM;
    const int bcol = blockIdx.x * GBN;

    const int tr = (tid / 16) * 8;   // thread tile row within block
    const int tc = (tid % 16) * 8;   // thread tile col within block

    // load mapping: each thread moves 2 float4 of A and 2 of B per k-step
    const int lr  = tid / 4;         // 0..63
    const int lc4 = tid % 4;         // k-chunk (float4)

    float acc[8][8];
    #pragma unroll
    for (int i = 0; i < 8; i++)
        #pragma unroll
        for (int j = 0; j < 8; j++) acc[i][j] = 0.f;

    for (int k0 = 0; k0 < K; k0 += GBK) {
        #pragma unroll
        for (int h = 0; h < 2; h++) {
            int row = lr + h * 64;
            float4 va = *(const float4*)(A + (size_t)(brow + row) * K + k0 + lc4 * 4);
            As[lc4*4+0][row] = va.x; As[lc4*4+1][row] = va.y;
            As[lc4*4+2][row] = va.z; As[lc4*4+3][row] = va.w;
            float4 vb = *(const float4*)(B + (size_t)(bcol + row) * K + k0 + lc4 * 4);
            Bs[lc4*4+0][row] = vb.x; Bs[lc4*4+1][row] = vb.y;
            Bs[lc4*4+2][row] = vb.z; Bs[lc4*4+3][row] = vb.w;
        }
        __syncthreads();

        #pragma unroll
        for (int k = 0; k < GBK; k++) {
            float ra[8], rb[8];
            #pragma unroll
            for (int i = 0; i < 8; i++) ra[i] = As[k][tr + i];
            #pragma unroll
            for (int j = 0; j < 8; j++) rb[j] = Bs[k][tc + j];
            #pragma unroll
            for (int i = 0; i < 8; i++)
                #pragma unroll
                for (int j = 0; j < 8; j++)
                    acc[i][j] = fmaf(ra[i], rb[j], acc[i][j]);
        }
        __syncthreads();
    }

    #pragma unroll
    for (int i = 0; i < 8; i++) {
        float4* cp = (float4*)(C + (size_t)(brow + tr + i) * N + bcol + tc);
        cp[0] = make_float4(acc[i][0], acc[i][1], acc[i][2], acc[i][3]);
        cp[1] = make_float4(acc[i][4], acc[i][5], acc[i][6], acc[i][7]);
    }
}

// ---------------------------------------------------------------------------
// RoPE: in-place on [B*T, nh, 64] rows; half-pairs (d, d+32)
// ---------------------------------------------------------------------------
__global__ void rope_kernel(float* __restrict__ q,
                            const float* __restrict__ cost,
                            const float* __restrict__ sint,
                            int rowsHeads, int nh)
{
    int idx = blockIdx.x * blockDim.x + threadIdx.x;
    int total = rowsHeads * 32;
    if (idx >= total) return;
    int d  = idx & 31;
    int rh = idx >> 5;          // (b*T + t)*nh + h
    int bt = rh / nh;
    int t  = bt & (TT - 1);     // T = 2048 power of 2
    float c = cost[t * HD + d];
    float s = sint[t * HD + d];
    float* base = q + (size_t)rh * HD;
    float x1 = base[d];
    float x2 = base[d + 32];
    base[d]      = fmaf(x1, c, -x2 * s);
    base[d + 32] = fmaf(x2, c,  x1 * s);
}

// ---------------------------------------------------------------------------
// Causal flash attention, fp32. One thread owns one q row (whole head dim
// in registers). Block = 128 threads = 128 q rows. K/V tiles of 32 rows in
// shared memory. Online softmax.
// Q,O layout: [B*T][NH*64];  K,V layout: [B*T][NKV*64]
// ---------------------------------------------------------------------------
#define AQ 128   // q rows per block
#define AK 32    // k rows per tile

__global__ __launch_bounds__(128) void attn_kernel(
    const float* __restrict__ Q, const float* __restrict__ Kg,
    const float* __restrict__ Vg, float* __restrict__ O)
{
    __shared__ float Ks[AK][HD];
    __shared__ float Vs[AK][HD];

    const int tid = threadIdx.x;
    const int qt  = blockIdx.x;
    const int bh  = blockIdx.y;
    const int b   = bh >> 5;         // NH = 32
    const int h   = bh & 31;
    const int kv  = h >> 2;          // NH/NKV = 4
    const int t   = qt * AQ + tid;

    const float scale = 0.125f;      // 1/sqrt(64)

    float qreg[HD];
    const float* qp = Q + ((size_t)(b * TT + t) * NH + h) * HD;
    #pragma unroll
    for (int d = 0; d < HD; d++) qreg[d] = qp[d] * scale;

    float o[HD];
    #pragma unroll
    for (int d = 0; d < HD; d++) o[d] = 0.f;
    float m = -INFINITY, l = 0.f;

    const int kmax = qt * AQ + AQ;   // exclusive

    // tile-load mapping: 8 rows x 16 float4 per pass, 4 passes
    const int lrow = tid >> 4;       // 0..7
    const int lc4  = tid & 15;       // float4 col

    for (int k0 = 0; k0 < kmax; k0 += AK) {
        #pragma unroll
        for (int i = 0; i < 4; i++) {
            int r = lrow + i * 8;
            size_t gro = ((size_t)(b * TT + k0 + r) * NKV + kv) * HD;
            ((float4*)Ks[r])[lc4] = ((const float4*)(Kg + gro))[lc4];
            ((float4*)Vs[r])[lc4] = ((const float4*)(Vg + gro))[lc4];
        }
        __syncthreads();

        float s[AK];
        #pragma unroll 4
        for (int kk = 0; kk < AK; kk++) {
            const float4* kr = (const float4*)Ks[kk];
            float a0 = 0.f, a1 = 0.f, a2 = 0.f, a3 = 0.f;
            #pragma unroll
            for (int d4 = 0; d4 < HD / 4; d4++) {
                float4 kvv = kr[d4];
                a0 = fmaf(qreg[d4*4+0], kvv.x, a0);
                a1 = fmaf(qreg[d4*4+1], kvv.y, a1);
                a2 = fmaf(qreg[d4*4+2], kvv.z, a2);
                a3 = fmaf(qreg[d4*4+3], kvv.w, a3);
            }
            s[kk] = (a0 + a1) + (a2 + a3);
        }

        if (k0 + AK > t + 1) {      // tile touches the causal boundary
            #pragma unroll
            for (int kk = 0; kk < AK; kk++)
                if (k0 + kk > t) s[kk] = -INFINITY;
        }

        float tm = m;
        #pragma unroll
        for (int kk = 0; kk < AK; kk++) tm = fmaxf(tm, s[kk]);
        float corr = __expf(m - tm);
        m = tm;
        l *= corr;
        #pragma unroll
        for (int d = 0; d < HD; d++) o[d] *= corr;

        #pragma unroll 2
        for (int kk = 0; kk < AK; kk++) {
            float p = __expf(s[kk] - m);
            l += p;
            const float4* vr = (const float4*)Vs[kk];
            #pragma unroll
            for (int d4 = 0; d4 < HD / 4; d4++) {
                float4 vv = vr[d4];
                o[d4*4+0] = fmaf(p, vv.x, o[d4*4+0]);
                o[d4*4+1] = fmaf(p, vv.y, o[d4*4+1]);
                o[d4*4+2] = fmaf(p, vv.z, o[d4*4+2]);
                o[d4*4+3] = fmaf(p, vv.w, o[d4*4+3]);
            }
        }
        __syncthreads();
    }

    float inv = 1.f / l;
    float* op = g_att + ((size_t)(b * TT + t) * NH + h) * HD;
    (void)O;
    #pragma unroll
    for (int d = 0; d < HD; d++) op[d] = o[d] * inv;
}

// ---------------------------------------------------------------------------
// Launch
// ---------------------------------------------------------------------------
extern "C" void kernel_launch(void* const* d_in, const int* in_sizes, int n_in,
                              void* d_out, int out_size)
{
    const float* x    = (const float*)d_in[0];
    const float* cosv = (const float*)d_in[1];
    const float* sinv = (const float*)d_in[2];
    const float* Wq   = (const float*)d_in[3];
    const float* Wk   = (const float*)d_in[4];
    const float* Wv   = (const float*)d_in[5];
    const float* Wo   = (const float*)d_in[6];
    float* out = (float*)d_out;

    float *q, *k, *v, *att;
    cudaGetSymbolAddress((void**)&q,   g_q);
    cudaGetSymbolAddress((void**)&k,   g_k);
    cudaGetSymbolAddress((void**)&v,   g_v);
    cudaGetSymbolAddress((void**)&att, g_att);

    // Projections: q = x @ Wq^T, k = x @ Wk^T, v = x @ Wv^T
    gemm_nt<<<dim3((NH*HD)/GBN,  MROWS/GBM), 256>>>(x, Wq, q, MROWS, NH*HD,  DM);
    gemm_nt<<<dim3((NKV*HD)/GBN, MROWS/GBM), 256>>>(x, Wk, k, MROWS, NKV*HD, DM);
    gemm_nt<<<dim3((NKV*HD)/GBN, MROWS/GBM), 256>>>(x, Wv, v, MROWS, NKV*HD, DM);

    // RoPE in place on q and k
    {
        int total_q = MROWS * NH * 32;
        rope_kernel<<<(total_q + 255) / 256, 256>>>(q, cosv, sinv, MROWS * NH, NH);
        int total_k = MROWS * NKV * 32;
        rope_kernel<<<(total_k + 255) / 256, 256>>>(k, cosv, sinv, MROWS * NKV, NKV);
    }

    // Causal attention -> att [B*T][NH*HD]
    attn_kernel<<<dim3(TT / AQ, BB * NH), 128>>>(q, k, v, att);

    // Output projection: out = att @ Wo^T
    gemm_nt<<<dim3(DM/GBN, MROWS/GBM), 256>>>(att, Wo, out, MROWS, DM, DM);
}

// round 6
// speedup vs baseline: 1.3873x; 1.3873x over previous
#include <cuda_runtime.h>
#include <cuda_bf16.h>
#include <math.h>
#include <stdint.h>

// Problem constants
#define BB 2
#define TT 2048
#define DM 2048
#define NH 32
#define NKV 8
#define HD 64
#define MROWS (BB*TT)          // 4096

// ---------------------------------------------------------------------------
// Scratch (device globals — no allocation allowed)
// ---------------------------------------------------------------------------
__device__ float g_q[MROWS * NH * HD];     // 32 MB
__device__ float g_k[MROWS * NKV * HD];    // 8 MB
__device__ float g_v[MROWS * NKV * HD];    // 8 MB
__device__ float g_att[MROWS * NH * HD];   // 32 MB

// split-bf16 operand buffers
__device__ __align__(16) __nv_bfloat16 g_xh[MROWS * DM];
__device__ __align__(16) __nv_bfloat16 g_xl[MROWS * DM];
__device__ __align__(16) __nv_bfloat16 g_wqh[NH*HD * DM];
__device__ __align__(16) __nv_bfloat16 g_wql[NH*HD * DM];
__device__ __align__(16) __nv_bfloat16 g_wkh[NKV*HD * DM];
__device__ __align__(16) __nv_bfloat16 g_wkl[NKV*HD * DM];
__device__ __align__(16) __nv_bfloat16 g_wvh[NKV*HD * DM];
__device__ __align__(16) __nv_bfloat16 g_wvl[NKV*HD * DM];
__device__ __align__(16) __nv_bfloat16 g_woh[DM * NH*HD];
__device__ __align__(16) __nv_bfloat16 g_wol[DM * NH*HD];
__device__ __align__(16) __nv_bfloat16 g_ah[MROWS * NH*HD];
__device__ __align__(16) __nv_bfloat16 g_al[MROWS * NH*HD];

// ---------------------------------------------------------------------------
// mma.sync helpers (target-portable: no sm_103a-only features)
// ---------------------------------------------------------------------------
__device__ __forceinline__ uint32_t smem_u32(const void* p) {
    uint32_t a;
    asm("{ .reg .u64 t; cvta.to.shared.u64 t, %1; cvt.u32.u64 %0, t; }" : "=r"(a) : "l"(p));
    return a;
}

__device__ __forceinline__ void ldsm_x4(uint32_t* r, uint32_t addr) {
    asm volatile("ldmatrix.sync.aligned.m8n8.x4.shared.b16 {%0,%1,%2,%3}, [%4];"
        : "=r"(r[0]), "=r"(r[1]), "=r"(r[2]), "=r"(r[3]) : "r"(addr));
}
__device__ __forceinline__ void ldsm_x2(uint32_t* r, uint32_t addr) {
    asm volatile("ldmatrix.sync.aligned.m8n8.x2.shared.b16 {%0,%1}, [%2];"
        : "=r"(r[0]), "=r"(r[1]) : "r"(addr));
}
__device__ __forceinline__ void mma16816(float* d, const uint32_t* a, const uint32_t* b) {
    asm volatile("mma.sync.aligned.m16n8k16.row.col.f32.bf16.bf16.f32 "
        "{%0,%1,%2,%3}, {%4,%5,%6,%7}, {%8,%9}, {%0,%1,%2,%3};"
        : "+f"(d[0]), "+f"(d[1]), "+f"(d[2]), "+f"(d[3])
        : "r"(a[0]), "r"(a[1]), "r"(a[2]), "r"(a[3]), "r"(b[0]), "r"(b[1]));
}

// ---------------------------------------------------------------------------
// Split-bf16 conversion: f = hi + lo
// ---------------------------------------------------------------------------
__global__ void cvt_split(const float* __restrict__ src,
                          __nv_bfloat16* __restrict__ hi,
                          __nv_bfloat16* __restrict__ lo, int n)
{
    int i = blockIdx.x * blockDim.x + threadIdx.x;
    if (i >= n) return;
    float f = src[i];
    __nv_bfloat16 h = __float2bfloat16(f);
    float r = f - __bfloat162float(h);
    hi[i] = h;
    lo[i] = __float2bfloat16(r);
}

// ---------------------------------------------------------------------------
// Tensor-core split-bf16 GEMM (NT): C[M,N] = A[M,K]*B[N,K]^T, ~fp32 precision
// via Ah*Bh + Ah*Bl + Al*Bh using mma.sync m16n8k16 bf16.
// 128x128 CTA tile, BK=32, 256 threads (8 warps), 64x32 warp tiles.
// ---------------------------------------------------------------------------
#define GBM 128
#define GBN 128
#define GBK 32
#define LDS 40                      // smem row stride in bf16 elems (32 + 8 pad)
#define TILE_B (GBM * LDS * 2)      // bytes per operand tile (10240)
#define OFF_AH 0
#define OFF_AL (TILE_B)
#define OFF_BH (2*TILE_B)
#define OFF_BL (3*TILE_B)
#define GEMM_SMEM (4*TILE_B)        // 40960 B

__global__ __launch_bounds__(256) void gemm_tc(
    const __nv_bfloat16* __restrict__ Ahg, const __nv_bfloat16* __restrict__ Alg,
    const __nv_bfloat16* __restrict__ Bhg, const __nv_bfloat16* __restrict__ Blg,
    float* __restrict__ C, int M, int N, int K)
{
    extern __shared__ char smem[];
    const uint32_t sb = smem_u32(smem);

    const int tid  = threadIdx.x;
    const int wid  = tid >> 5;
    const int lane = tid & 31;
    const int wm   = wid & 1;        // 2 warp-rows of 64
    const int wn   = wid >> 1;       // 4 warp-cols of 32

    const int brow = blockIdx.y * GBM;
    const int bcol = blockIdx.x * GBN;

    // per-lane ldmatrix base offsets (bytes)
    // A: row = wm*64 + mi*16 + (lane&15), kbyte = (lane>>4)*16
    const uint32_t aoff = (uint32_t)((wm*64 + (lane & 15)) * (LDS*2) + (lane >> 4) * 16);
    // B: row(n) = wn*32 + ni*8 + (lane&7), kbyte = ((lane>>3)&1)*16
    const uint32_t boff = (uint32_t)((wn*32 + (lane & 7)) * (LDS*2) + ((lane >> 3) & 1) * 16);

    float acc[4][4][4];
    #pragma unroll
    for (int mi = 0; mi < 4; mi++)
        #pragma unroll
        for (int ni = 0; ni < 4; ni++)
            #pragma unroll
            for (int r = 0; r < 4; r++) acc[mi][ni][r] = 0.f;

    for (int k0 = 0; k0 < K; k0 += GBK) {
        // global -> smem: 4 tiles of 128x32 bf16; 2 uint4 per thread per tile
        #pragma unroll
        for (int i = 0; i < 2; i++) {
            int idx = tid + i * 256;             // 0..511
            int r   = idx >> 2;                  // row 0..127
            int c8  = idx & 3;                   // 8-elem chunk
            size_t ga = (size_t)(brow + r) * K + k0 + c8 * 8;
            size_t gb = (size_t)(bcol + r) * K + k0 + c8 * 8;
            uint32_t so = (uint32_t)(r * (LDS*2) + c8 * 16);
            *(uint4*)(smem + OFF_AH + so) = *(const uint4*)(Ahg + ga);
            *(uint4*)(smem + OFF_AL + so) = *(const uint4*)(Alg + ga);
            *(uint4*)(smem + OFF_BH + so) = *(const uint4*)(Bhg + gb);
            *(uint4*)(smem + OFF_BL + so) = *(const uint4*)(Blg + gb);
        }
        __syncthreads();

        #pragma unroll
        for (int kk = 0; kk < GBK; kk += 16) {
            const uint32_t kb = kk * 2;          // byte offset along k

            uint32_t ah[4][4], bh[4][2];
            #pragma unroll
            for (int mi = 0; mi < 4; mi++)
                ldsm_x4(ah[mi], sb + OFF_AH + aoff + mi * 16 * (LDS*2) + kb);
            #pragma unroll
            for (int ni = 0; ni < 4; ni++)
                ldsm_x2(bh[ni], sb + OFF_BH + boff + ni * 8 * (LDS*2) + kb);

            // pass 1: Ah * Bh
            #pragma unroll
            for (int mi = 0; mi < 4; mi++)
                #pragma unroll
                for (int ni = 0; ni < 4; ni++)
                    mma16816(acc[mi][ni], ah[mi], bh[ni]);

            // pass 2: Ah * Bl
            {
                uint32_t bl[4][2];
                #pragma unroll
                for (int ni = 0; ni < 4; ni++)
                    ldsm_x2(bl[ni], sb + OFF_BL + boff + ni * 8 * (LDS*2) + kb);
                #pragma unroll
                for (int mi = 0; mi < 4; mi++)
                    #pragma unroll
                    for (int ni = 0; ni < 4; ni++)
                        mma16816(acc[mi][ni], ah[mi], bl[ni]);
            }

            // pass 3: Al * Bh
            {
                uint32_t al[4][4];
                #pragma unroll
                for (int mi = 0; mi < 4; mi++)
                    ldsm_x4(al[mi], sb + OFF_AL + aoff + mi * 16 * (LDS*2) + kb);
                #pragma unroll
                for (int mi = 0; mi < 4; mi++)
                    #pragma unroll
                    for (int ni = 0; ni < 4; ni++)
                        mma16816(acc[mi][ni], al[mi], bh[ni]);
            }
        }
        __syncthreads();
    }

    // epilogue: d0,d1 -> row lane/4, cols (lane%4)*2+{0,1}; d2,d3 -> row+8
    const int er = lane >> 2;
    const int ec = (lane & 3) * 2;
    #pragma unroll
    for (int mi = 0; mi < 4; mi++) {
        #pragma unroll
        for (int ni = 0; ni < 4; ni++) {
            int row = brow + wm*64 + mi*16 + er;
            int col = bcol + wn*32 + ni*8 + ec;
            float2* p0 = (float2*)(C + (size_t)row * N + col);
            float2* p1 = (float2*)(C + (size_t)(row + 8) * N + col);
            *p0 = make_float2(acc[mi][ni][0], acc[mi][ni][1]);
            *p1 = make_float2(acc[mi][ni][2], acc[mi][ni][3]);
        }
    }
}

// ---------------------------------------------------------------------------
// RoPE: in-place on [B*T, nh, 64] rows; half-pairs (d, d+32)
// ---------------------------------------------------------------------------
__global__ void rope_kernel(float* __restrict__ q,
                            const float* __restrict__ cost,
                            const float* __restrict__ sint,
                            int rowsHeads, int nh)
{
    int idx = blockIdx.x * blockDim.x + threadIdx.x;
    int total = rowsHeads * 32;
    if (idx >= total) return;
    int d  = idx & 31;
    int rh = idx >> 5;
    int bt = rh / nh;
    int t  = bt & (TT - 1);
    float c = cost[t * HD + d];
    float s = sint[t * HD + d];
    float* base = q + (size_t)rh * HD;
    float x1 = base[d];
    float x2 = base[d + 32];
    base[d]      = fmaf(x1, c, -x2 * s);
    base[d + 32] = fmaf(x2, c,  x1 * s);
}

// ---------------------------------------------------------------------------
// Causal flash attention, fp32 (known-good from R1/R2)
// ---------------------------------------------------------------------------
#define AQ 128
#define AK 32

__global__ __launch_bounds__(128) void attn_kernel(
    const float* __restrict__ Q, const float* __restrict__ Kg,
    const float* __restrict__ Vg, float* __restrict__ O)
{
    __shared__ float Ks[AK][HD];
    __shared__ float Vs[AK][HD];

    const int tid = threadIdx.x;
    const int qt  = blockIdx.x;
    const int bh  = blockIdx.y;
    const int b   = bh >> 5;
    const int h   = bh & 31;
    const int kv  = h >> 2;
    const int t   = qt * AQ + tid;

    const float scale = 0.125f;

    float qreg[HD];
    const float* qp = Q + ((size_t)(b * TT + t) * NH + h) * HD;
    #pragma unroll
    for (int d = 0; d < HD; d++) qreg[d] = qp[d] * scale;

    float o[HD];
    #pragma unroll
    for (int d = 0; d < HD; d++) o[d] = 0.f;
    float m = -INFINITY, l = 0.f;

    const int kmax = qt * AQ + AQ;
    const int lrow = tid >> 4;
    const int lc4  = tid & 15;

    for (int k0 = 0; k0 < kmax; k0 += AK) {
        #pragma unroll
        for (int i = 0; i < 4; i++) {
            int r = lrow + i * 8;
            size_t gro = ((size_t)(b * TT + k0 + r) * NKV + kv) * HD;
            ((float4*)Ks[r])[lc4] = ((const float4*)(Kg + gro))[lc4];
            ((float4*)Vs[r])[lc4] = ((const float4*)(Vg + gro))[lc4];
        }
        __syncthreads();

        float s[AK];
        #pragma unroll 4
        for (int kk = 0; kk < AK; kk++) {
            const float4* kr = (const float4*)Ks[kk];
            float a0 = 0.f, a1 = 0.f, a2 = 0.f, a3 = 0.f;
            #pragma unroll
            for (int d4 = 0; d4 < HD / 4; d4++) {
                float4 kvv = kr[d4];
                a0 = fmaf(qreg[d4*4+0], kvv.x, a0);
                a1 = fmaf(qreg[d4*4+1], kvv.y, a1);
                a2 = fmaf(qreg[d4*4+2], kvv.z, a2);
                a3 = fmaf(qreg[d4*4+3], kvv.w, a3);
            }
            s[kk] = (a0 + a1) + (a2 + a3);
        }

        if (k0 + AK > t + 1) {
            #pragma unroll
            for (int kk = 0; kk < AK; kk++)
                if (k0 + kk > t) s[kk] = -INFINITY;
        }

        float tm = m;
        #pragma unroll
        for (int kk = 0; kk < AK; kk++) tm = fmaxf(tm, s[kk]);
        float corr = __expf(m - tm);
        m = tm;
        l *= corr;
        #pragma unroll
        for (int d = 0; d < HD; d++) o[d] *= corr;

        #pragma unroll 2
        for (int kk = 0; kk < AK; kk++) {
            float p = __expf(s[kk] - m);
            l += p;
            const float4* vr = (const float4*)Vs[kk];
            #pragma unroll
            for (int d4 = 0; d4 < HD / 4; d4++) {
                float4 vv = vr[d4];
                o[d4*4+0] = fmaf(p, vv.x, o[d4*4+0]);
                o[d4*4+1] = fmaf(p, vv.y, o[d4*4+1]);
                o[d4*4+2] = fmaf(p, vv.z, o[d4*4+2]);
                o[d4*4+3] = fmaf(p, vv.w, o[d4*4+3]);
            }
        }
        __syncthreads();
    }

    float inv = 1.f / l;
    float* op = g_att + ((size_t)(b * TT + t) * NH + h) * HD;
    (void)O;
    #pragma unroll
    for (int d = 0; d < HD; d++) op[d] = o[d] * inv;
}

// ---------------------------------------------------------------------------
// Launch
// ---------------------------------------------------------------------------
extern "C" void kernel_launch(void* const* d_in, const int* in_sizes, int n_in,
                              void* d_out, int out_size)
{
    const float* x    = (const float*)d_in[0];
    const float* cosv = (const float*)d_in[1];
    const float* sinv = (const float*)d_in[2];
    const float* Wq   = (const float*)d_in[3];
    const float* Wk   = (const float*)d_in[4];
    const float* Wv   = (const float*)d_in[5];
    const float* Wo   = (const float*)d_in[6];
    float* out = (float*)d_out;

    float *q, *k, *v, *att;
    cudaGetSymbolAddress((void**)&q,   g_q);
    cudaGetSymbolAddress((void**)&k,   g_k);
    cudaGetSymbolAddress((void**)&v,   g_v);
    cudaGetSymbolAddress((void**)&att, g_att);

    __nv_bfloat16 *xh, *xl, *wqh, *wql, *wkh, *wkl, *wvh, *wvl, *woh, *wol, *ah, *al;
    cudaGetSymbolAddress((void**)&xh,  g_xh);   cudaGetSymbolAddress((void**)&xl,  g_xl);
    cudaGetSymbolAddress((void**)&wqh, g_wqh);  cudaGetSymbolAddress((void**)&wql, g_wql);
    cudaGetSymbolAddress((void**)&wkh, g_wkh);  cudaGetSymbolAddress((void**)&wkl, g_wkl);
    cudaGetSymbolAddress((void**)&wvh, g_wvh);  cudaGetSymbolAddress((void**)&wvl, g_wvl);
    cudaGetSymbolAddress((void**)&woh, g_woh);  cudaGetSymbolAddress((void**)&wol, g_wol);
    cudaGetSymbolAddress((void**)&ah,  g_ah);   cudaGetSymbolAddress((void**)&al,  g_al);

    // defensive: allow our dynamic smem size explicitly
    cudaFuncSetAttribute(gemm_tc, cudaFuncAttributeMaxDynamicSharedMemorySize, GEMM_SMEM);

    // split conversions
    {
        int n;
        n = MROWS * DM;     cvt_split<<<(n+255)/256, 256>>>(x,  xh,  xl,  n);
        n = NH*HD * DM;     cvt_split<<<(n+255)/256, 256>>>(Wq, wqh, wql, n);
        n = NKV*HD * DM;    cvt_split<<<(n+255)/256, 256>>>(Wk, wkh, wkl, n);
        n = NKV*HD * DM;    cvt_split<<<(n+255)/256, 256>>>(Wv, wvh, wvl, n);
        n = DM * NH*HD;     cvt_split<<<(n+255)/256, 256>>>(Wo, woh, wol, n);
    }

    // projections on tensor cores (mma.sync path)
    gemm_tc<<<dim3((NH*HD)/GBN,  MROWS/GBM), 256, GEMM_SMEM>>>(xh, xl, wqh, wql, q, MROWS, NH*HD,  DM);
    gemm_tc<<<dim3((NKV*HD)/GBN, MROWS/GBM), 256, GEMM_SMEM>>>(xh, xl, wkh, wkl, k, MROWS, NKV*HD, DM);
    gemm_tc<<<dim3((NKV*HD)/GBN, MROWS/GBM), 256, GEMM_SMEM>>>(xh, xl, wvh, wvl, v, MROWS, NKV*HD, DM);

    // RoPE in place
    {
        int total_q = MROWS * NH * 32;
        rope_kernel<<<(total_q + 255) / 256, 256>>>(q, cosv, sinv, MROWS * NH, NH);
        int total_k = MROWS * NKV * 32;
        rope_kernel<<<(total_k + 255) / 256, 256>>>(k, cosv, sinv, MROWS * NKV, NKV);
    }

    // causal attention -> g_att
    attn_kernel<<<dim3(TT / AQ, BB * NH), 128>>>(q, k, v, att);

    // split att, output projection on tensor cores
    {
        int n = MROWS * NH*HD;
        cvt_split<<<(n+255)/256, 256>>>(att, ah, al, n);
    }
    gemm_tc<<<dim3(DM/GBN, MROWS/GBM), 256, GEMM_SMEM>>>(ah, al, woh, wol, out, MROWS, DM, DM);
}

// round 8
// speedup vs baseline: 2.1290x; 1.5346x over previous
#include <cuda_runtime.h>
#include <cuda_bf16.h>
#include <math.h>
#include <stdint.h>

// Problem constants
#define BB 2
#define TT 2048
#define DM 2048
#define NH 32
#define NKV 8
#define HD 64
#define MROWS (BB*TT)          // 4096

// ---------------------------------------------------------------------------
// Scratch (device globals — no allocation allowed)
// ---------------------------------------------------------------------------
__device__ float g_q[MROWS * NH * HD];     // fp32 projection outputs
__device__ float g_k[MROWS * NKV * HD];
__device__ float g_v[MROWS * NKV * HD];

// split-bf16 operand buffers
__device__ __align__(16) __nv_bfloat16 g_xh[MROWS * DM];
__device__ __align__(16) __nv_bfloat16 g_xl[MROWS * DM];
__device__ __align__(16) __nv_bfloat16 g_wqh[NH*HD * DM];
__device__ __align__(16) __nv_bfloat16 g_wql[NH*HD * DM];
__device__ __align__(16) __nv_bfloat16 g_wkh[NKV*HD * DM];
__device__ __align__(16) __nv_bfloat16 g_wkl[NKV*HD * DM];
__device__ __align__(16) __nv_bfloat16 g_wvh[NKV*HD * DM];
__device__ __align__(16) __nv_bfloat16 g_wvl[NKV*HD * DM];
__device__ __align__(16) __nv_bfloat16 g_woh[DM * NH*HD];
__device__ __align__(16) __nv_bfloat16 g_wol[DM * NH*HD];
__device__ __align__(16) __nv_bfloat16 g_ah[MROWS * NH*HD];   // attn out split
__device__ __align__(16) __nv_bfloat16 g_al[MROWS * NH*HD];

// split bf16 q/k/v for attention (post-rope)
__device__ __align__(16) __nv_bfloat16 g_qsh[MROWS * NH * HD];
__device__ __align__(16) __nv_bfloat16 g_qsl[MROWS * NH * HD];
__device__ __align__(16) __nv_bfloat16 g_ksh[MROWS * NKV * HD];
__device__ __align__(16) __nv_bfloat16 g_ksl[MROWS * NKV * HD];
__device__ __align__(16) __nv_bfloat16 g_vsh[MROWS * NKV * HD];
__device__ __align__(16) __nv_bfloat16 g_vsl[MROWS * NKV * HD];

// ---------------------------------------------------------------------------
// mma.sync helpers (target-portable)
// ---------------------------------------------------------------------------
__device__ __forceinline__ uint32_t smem_u32(const void* p) {
    uint32_t a;
    asm("{ .reg .u64 t; cvta.to.shared.u64 t, %1; cvt.u32.u64 %0, t; }" : "=r"(a) : "l"(p));
    return a;
}
__device__ __forceinline__ void ldsm_x4(uint32_t* r, uint32_t addr) {
    asm volatile("ldmatrix.sync.aligned.m8n8.x4.shared.b16 {%0,%1,%2,%3}, [%4];"
        : "=r"(r[0]), "=r"(r[1]), "=r"(r[2]), "=r"(r[3]) : "r"(addr));
}
__device__ __forceinline__ void ldsm_x2(uint32_t* r, uint32_t addr) {
    asm volatile("ldmatrix.sync.aligned.m8n8.x2.shared.b16 {%0,%1}, [%2];"
        : "=r"(r[0]), "=r"(r[1]) : "r"(addr));
}
__device__ __forceinline__ void mma16816(float* d, const uint32_t* a, const uint32_t* b) {
    asm volatile("mma.sync.aligned.m16n8k16.row.col.f32.bf16.bf16.f32 "
        "{%0,%1,%2,%3}, {%4,%5,%6,%7}, {%8,%9}, {%0,%1,%2,%3};"
        : "+f"(d[0]), "+f"(d[1]), "+f"(d[2]), "+f"(d[3])
        : "r"(a[0]), "r"(a[1]), "r"(a[2]), "r"(a[3]), "r"(b[0]), "r"(b[1]));
}
__device__ __forceinline__ uint32_t pack_bf16(float x, float y) {
    __nv_bfloat16 hx = __float2bfloat16(x), hy = __float2bfloat16(y);
    uint16_t ux = *(uint16_t*)&hx, uy = *(uint16_t*)&hy;
    return (uint32_t)ux | ((uint32_t)uy << 16);
}
// split x,y into hi/lo bf16x2 packs
__device__ __forceinline__ void split_pack(float x, float y, uint32_t& hi, uint32_t& lo) {
    __nv_bfloat16 hx = __float2bfloat16(x), hy = __float2bfloat16(y);
    float rx = x - __bfloat162float(hx);
    float ry = y - __bfloat162float(hy);
    hi = (uint32_t)(*(uint16_t*)&hx) | ((uint32_t)(*(uint16_t*)&hy) << 16);
    __nv_bfloat16 lx = __float2bfloat16(rx), ly = __float2bfloat16(ry);
    lo = (uint32_t)(*(uint16_t*)&lx) | ((uint32_t)(*(uint16_t*)&ly) << 16);
}

// ---------------------------------------------------------------------------
// Split-bf16 conversion: f = hi + lo
// ---------------------------------------------------------------------------
__global__ void cvt_split(const float* __restrict__ src,
                          __nv_bfloat16* __restrict__ hi,
                          __nv_bfloat16* __restrict__ lo, int n)
{
    int i = blockIdx.x * blockDim.x + threadIdx.x;
    if (i >= n) return;
    float f = src[i];
    __nv_bfloat16 h = __float2bfloat16(f);
    float r = f - __bfloat162float(h);
    hi[i] = h;
    lo[i] = __float2bfloat16(r);
}

// ---------------------------------------------------------------------------
// Tensor-core split-bf16 GEMM (NT) — unchanged from R6 (passing)
// ---------------------------------------------------------------------------
#define GBM 128
#define GBN 128
#define GBK 32
#define LDS 40
#define TILE_B (GBM * LDS * 2)
#define OFF_AH 0
#define OFF_AL (TILE_B)
#define OFF_BH (2*TILE_B)
#define OFF_BL (3*TILE_B)
#define GEMM_SMEM (4*TILE_B)

__global__ __launch_bounds__(256) void gemm_tc(
    const __nv_bfloat16* __restrict__ Ahg, const __nv_bfloat16* __restrict__ Alg,
    const __nv_bfloat16* __restrict__ Bhg, const __nv_bfloat16* __restrict__ Blg,
    float* __restrict__ C, int M, int N, int K)
{
    extern __shared__ char smem[];
    const uint32_t sb = smem_u32(smem);

    const int tid  = threadIdx.x;
    const int wid  = tid >> 5;
    const int lane = tid & 31;
    const int wm   = wid & 1;
    const int wn   = wid >> 1;

    const int brow = blockIdx.y * GBM;
    const int bcol = blockIdx.x * GBN;

    const uint32_t aoff = (uint32_t)((wm*64 + (lane & 15)) * (LDS*2) + (lane >> 4) * 16);
    const uint32_t boff = (uint32_t)((wn*32 + (lane & 7)) * (LDS*2) + ((lane >> 3) & 1) * 16);

    float acc[4][4][4];
    #pragma unroll
    for (int mi = 0; mi < 4; mi++)
        #pragma unroll
        for (int ni = 0; ni < 4; ni++)
            #pragma unroll
            for (int r = 0; r < 4; r++) acc[mi][ni][r] = 0.f;

    for (int k0 = 0; k0 < K; k0 += GBK) {
        #pragma unroll
        for (int i = 0; i < 2; i++) {
            int idx = tid + i * 256;
            int r   = idx >> 2;
            int c8  = idx & 3;
            size_t ga = (size_t)(brow + r) * K + k0 + c8 * 8;
            size_t gb = (size_t)(bcol + r) * K + k0 + c8 * 8;
            uint32_t so = (uint32_t)(r * (LDS*2) + c8 * 16);
            *(uint4*)(smem + OFF_AH + so) = *(const uint4*)(Ahg + ga);
            *(uint4*)(smem + OFF_AL + so) = *(const uint4*)(Alg + ga);
            *(uint4*)(smem + OFF_BH + so) = *(const uint4*)(Bhg + gb);
            *(uint4*)(smem + OFF_BL + so) = *(const uint4*)(Blg + gb);
        }
        __syncthreads();

        #pragma unroll
        for (int kk = 0; kk < GBK; kk += 16) {
            const uint32_t kb = kk * 2;

            uint32_t ah[4][4], bh[4][2];
            #pragma unroll
            for (int mi = 0; mi < 4; mi++)
                ldsm_x4(ah[mi], sb + OFF_AH + aoff + mi * 16 * (LDS*2) + kb);
            #pragma unroll
            for (int ni = 0; ni < 4; ni++)
                ldsm_x2(bh[ni], sb + OFF_BH + boff + ni * 8 * (LDS*2) + kb);

            #pragma unroll
            for (int mi = 0; mi < 4; mi++)
                #pragma unroll
                for (int ni = 0; ni < 4; ni++)
                    mma16816(acc[mi][ni], ah[mi], bh[ni]);

            {
                uint32_t bl[4][2];
                #pragma unroll
                for (int ni = 0; ni < 4; ni++)
                    ldsm_x2(bl[ni], sb + OFF_BL + boff + ni * 8 * (LDS*2) + kb);
                #pragma unroll
                for (int mi = 0; mi < 4; mi++)
                    #pragma unroll
                    for (int ni = 0; ni < 4; ni++)
                        mma16816(acc[mi][ni], ah[mi], bl[ni]);
            }
            {
                uint32_t al[4][4];
                #pragma unroll
                for (int mi = 0; mi < 4; mi++)
                    ldsm_x4(al[mi], sb + OFF_AL + aoff + mi * 16 * (LDS*2) + kb);
                #pragma unroll
                for (int mi = 0; mi < 4; mi++)
                    #pragma unroll
                    for (int ni = 0; ni < 4; ni++)
                        mma16816(acc[mi][ni], al[mi], bh[ni]);
            }
        }
        __syncthreads();
    }

    const int er = lane >> 2;
    const int ec = (lane & 3) * 2;
    #pragma unroll
    for (int mi = 0; mi < 4; mi++) {
        #pragma unroll
        for (int ni = 0; ni < 4; ni++) {
            int row = brow + wm*64 + mi*16 + er;
            int col = bcol + wn*32 + ni*8 + ec;
            float2* p0 = (float2*)(C + (size_t)row * N + col);
            float2* p1 = (float2*)(C + (size_t)(row + 8) * N + col);
            *p0 = make_float2(acc[mi][ni][0], acc[mi][ni][1]);
            *p1 = make_float2(acc[mi][ni][2], acc[mi][ni][3]);
        }
    }
}

// ---------------------------------------------------------------------------
// RoPE fused with bf16 split (optionally scales by `scale`)
// ---------------------------------------------------------------------------
__global__ void rope_split(const float* __restrict__ src,
                           const float* __restrict__ cost,
                           const float* __restrict__ sint,
                           __nv_bfloat16* __restrict__ dh,
                           __nv_bfloat16* __restrict__ dl,
                           int rowsHeads, int nh, float scale)
{
    int idx = blockIdx.x * blockDim.x + threadIdx.x;
    int total = rowsHeads * 32;
    if (idx >= total) return;
    int d  = idx & 31;
    int rh = idx >> 5;
    int bt = rh / nh;
    int t  = bt & (TT - 1);
    float c = cost[t * HD + d];
    float s = sint[t * HD + d];
    const float* base = src + (size_t)rh * HD;
    float x1 = base[d];
    float x2 = base[d + 32];
    float y1 = fmaf(x1, c, -x2 * s) * scale;
    float y2 = fmaf(x2, c,  x1 * s) * scale;
    size_t o = (size_t)rh * HD;
    __nv_bfloat16 h1 = __float2bfloat16(y1);
    __nv_bfloat16 h2 = __float2bfloat16(y2);
    dh[o + d]      = h1;
    dh[o + d + 32] = h2;
    dl[o + d]      = __float2bfloat16(y1 - __bfloat162float(h1));
    dl[o + d + 32] = __float2bfloat16(y2 - __bfloat162float(h2));
}

// ---------------------------------------------------------------------------
// Flash attention on mma.sync, split-bf16 QK and PV.
// CTA: 128 threads (4 warps). Q tile 64 rows (warp w: rows w*16..+15).
// KV tiles of 64. V stored transposed in smem ([d][kv]).
// Outputs split bf16 directly into O-proj operand buffers.
// ---------------------------------------------------------------------------
#define ATQ 64
#define ATK 64
#define ASTR   72        // smem row stride (bf16 elems)
#define ASTRB  144       // bytes
#define S_QH 0
#define S_QL (64*ASTRB)
#define S_KH (2*64*ASTRB)
#define S_KL (3*64*ASTRB)
#define S_VH (4*64*ASTRB)   // transposed: rows d, cols kv
#define S_VL (5*64*ASTRB)
#define ATTN_SMEM (6*64*ASTRB)   // 55296 B

__global__ __launch_bounds__(128) void attn_tc(
    const __nv_bfloat16* __restrict__ qsh, const __nv_bfloat16* __restrict__ qsl,
    const __nv_bfloat16* __restrict__ ksh, const __nv_bfloat16* __restrict__ ksl,
    const __nv_bfloat16* __restrict__ vsh, const __nv_bfloat16* __restrict__ vsl,
    __nv_bfloat16* __restrict__ Ohg, __nv_bfloat16* __restrict__ Olg)
{
    extern __shared__ char smem[];
    const uint32_t sb = smem_u32(smem);
    const int tid  = threadIdx.x;
    const int wid  = tid >> 5;
    const int lane = tid & 31;

    const int qt = blockIdx.x;
    const int bh = blockIdx.y;
    const int b  = bh >> 5;
    const int h  = bh & 31;
    const int kv = h >> 2;
    const int q0 = qt * ATQ;

    // ---- load Q tile (64x64) split into smem ----
    #pragma unroll
    for (int i = 0; i < 4; i++) {
        int idx = tid + i * 128;        // 0..511
        int r   = idx >> 3;
        int c8  = idx & 7;
        size_t g = ((size_t)(b * TT + q0 + r) * NH + h) * HD + c8 * 8;
        uint32_t so = (uint32_t)(r * ASTRB + c8 * 16);
        *(uint4*)(smem + S_QH + so) = *(const uint4*)(qsh + g);
        *(uint4*)(smem + S_QL + so) = *(const uint4*)(qsl + g);
    }
    __syncthreads();

    // ---- per-warp Q fragments (held for whole kernel) ----
    uint32_t qh[4][4], ql[4][4];
    {
        uint32_t abase = (uint32_t)((wid*16 + (lane & 15)) * ASTRB + (lane >> 4) * 16);
        #pragma unroll
        for (int ks = 0; ks < 4; ks++) {
            ldsm_x4(qh[ks], sb + S_QH + abase + ks * 32);
            ldsm_x4(ql[ks], sb + S_QL + abase + ks * 32);
        }
    }

    float o[8][4];
    #pragma unroll
    for (int dt = 0; dt < 8; dt++)
        #pragma unroll
        for (int r = 0; r < 4; r++) o[dt][r] = 0.f;
    float m0 = -1e30f, m1 = -1e30f, l0 = 0.f, l1 = 0.f;

    const int ntiles = qt + 1;
    const uint32_t bbase = (uint32_t)((lane & 7) * ASTRB + ((lane >> 3) & 1) * 16);

    for (int kt = 0; kt < ntiles; kt++) {
        const int k0 = kt * ATK;
        __syncthreads();   // previous tile's smem consumers done

        // ---- load K tile split ----
        #pragma unroll
        for (int i = 0; i < 4; i++) {
            int idx = tid + i * 128;
            int r   = idx >> 3;
            int c8  = idx & 7;
            size_t g = ((size_t)(b * TT + k0 + r) * NKV + kv) * HD + c8 * 8;
            uint32_t so = (uint32_t)(r * ASTRB + c8 * 16);
            *(uint4*)(smem + S_KH + so) = *(const uint4*)(ksh + g);
            *(uint4*)(smem + S_KL + so) = *(const uint4*)(ksl + g);
        }
        // ---- load V tile split, transposed into smem [d][kv] ----
        #pragma unroll
        for (int i = 0; i < 4; i++) {
            int idx = tid + i * 128;
            int r   = idx >> 3;            // kv row
            int d0  = (idx & 7) * 8;       // d chunk
            size_t g = ((size_t)(b * TT + k0 + r) * NKV + kv) * HD + d0;
            uint4 vh4 = *(const uint4*)(vsh + g);
            uint4 vl4 = *(const uint4*)(vsl + g);
            const __nv_bfloat16* ph = (const __nv_bfloat16*)&vh4;
            const __nv_bfloat16* pl = (const __nv_bfloat16*)&vl4;
            #pragma unroll
            for (int e = 0; e < 8; e++) {
                *(__nv_bfloat16*)(smem + S_VH + (d0 + e) * ASTRB + r * 2) = ph[e];
                *(__nv_bfloat16*)(smem + S_VL + (d0 + e) * ASTRB + r * 2) = pl[e];
            }
        }
        __syncthreads();

        // ---- S = (Q K^T), split 3-pass ----
        float s[8][4];
        #pragma unroll
        for (int nt = 0; nt < 8; nt++)
            #pragma unroll
            for (int r = 0; r < 4; r++) s[nt][r] = 0.f;

        #pragma unroll
        for (int ks = 0; ks < 4; ks++) {
            #pragma unroll
            for (int nt = 0; nt < 8; nt++) {
                uint32_t kh2[2], kl2[2];
                uint32_t ka = sb + bbase + nt * 8 * ASTRB + ks * 32;
                ldsm_x2(kh2, S_KH + ka);
                ldsm_x2(kl2, S_KL + ka);
                mma16816(s[nt], qh[ks], kh2);
                mma16816(s[nt], qh[ks], kl2);
                mma16816(s[nt], ql[ks], kh2);
            }
        }

        // ---- causal mask (diagonal tile only) ----
        const int row0 = q0 + wid * 16 + (lane >> 2);
        const int row1 = row0 + 8;
        if (kt == qt) {
            #pragma unroll
            for (int nt = 0; nt < 8; nt++) {
                int col = k0 + nt * 8 + (lane & 3) * 2;
                if (col     > row0) s[nt][0] = -1e30f;
                if (col + 1 > row0) s[nt][1] = -1e30f;
                if (col     > row1) s[nt][2] = -1e30f;
                if (col + 1 > row1) s[nt][3] = -1e30f;
            }
        }

        // ---- online softmax ----
        float mx0 = m0, mx1 = m1;
        #pragma unroll
        for (int nt = 0; nt < 8; nt++) {
            mx0 = fmaxf(mx0, fmaxf(s[nt][0], s[nt][1]));
            mx1 = fmaxf(mx1, fmaxf(s[nt][2], s[nt][3]));
        }
        mx0 = fmaxf(mx0, __shfl_xor_sync(0xFFFFFFFF, mx0, 1));
        mx0 = fmaxf(mx0, __shfl_xor_sync(0xFFFFFFFF, mx0, 2));
        mx1 = fmaxf(mx1, __shfl_xor_sync(0xFFFFFFFF, mx1, 1));
        mx1 = fmaxf(mx1, __shfl_xor_sync(0xFFFFFFFF, mx1, 2));

        float c0 = __expf(m0 - mx0);
        float c1 = __expf(m1 - mx1);
        m0 = mx0; m1 = mx1;
        l0 *= c0;  l1 *= c1;
        #pragma unroll
        for (int dt = 0; dt < 8; dt++) {
            o[dt][0] *= c0; o[dt][1] *= c0;
            o[dt][2] *= c1; o[dt][3] *= c1;
        }

        // ---- P = exp(S - m), pack split A-fragments ----
        uint32_t pha[4][4], pla[4][4];
        float rs0 = 0.f, rs1 = 0.f;
        #pragma unroll
        for (int j = 0; j < 8; j++) {
            float p0 = __expf(s[j][0] - m0);
            float p1 = __expf(s[j][1] - m0);
            float p2 = __expf(s[j][2] - m1);
            float p3 = __expf(s[j][3] - m1);
            rs0 += p0 + p1;
            rs1 += p2 + p3;
            uint32_t hi01, lo01, hi23, lo23;
            split_pack(p0, p1, hi01, lo01);
            split_pack(p2, p3, hi23, lo23);
            int c = j >> 1;
            if ((j & 1) == 0) {
                pha[c][0] = hi01; pla[c][0] = lo01;
                pha[c][1] = hi23; pla[c][1] = lo23;
            } else {
                pha[c][2] = hi01; pla[c][2] = lo01;
                pha[c][3] = hi23; pla[c][3] = lo23;
            }
        }
        rs0 += __shfl_xor_sync(0xFFFFFFFF, rs0, 1);
        rs0 += __shfl_xor_sync(0xFFFFFFFF, rs0, 2);
        rs1 += __shfl_xor_sync(0xFFFFFFFF, rs1, 1);
        rs1 += __shfl_xor_sync(0xFFFFFFFF, rs1, 2);
        l0 += rs0;
        l1 += rs1;

        // ---- O += P V  (split 3-pass; V^T in smem, rows d) ----
        #pragma unroll
        for (int ks = 0; ks < 4; ks++) {
            #pragma unroll
            for (int dt = 0; dt < 8; dt++) {
                uint32_t vh2[2], vl2[2];
                uint32_t va = sb + bbase + dt * 8 * ASTRB + ks * 32;
                ldsm_x2(vh2, S_VH + va);
                ldsm_x2(vl2, S_VL + va);
                mma16816(o[dt], pha[ks], vh2);
                mma16816(o[dt], pha[ks], vl2);
                mma16816(o[dt], pla[ks], vh2);
            }
        }
    }

    // ---- finalize & write split output ----
    const float i0 = 1.f / l0;
    const float i1 = 1.f / l1;
    const int row0 = q0 + wid * 16 + (lane >> 2);
    const int row1 = row0 + 8;
    const int colb = h * HD + (lane & 3) * 2;
    #pragma unroll
    for (int dt = 0; dt < 8; dt++) {
        int col = colb + dt * 8;
        uint32_t hi0, lo0, hi1, lo1;
        split_pack(o[dt][0] * i0, o[dt][1] * i0, hi0, lo0);
        split_pack(o[dt][2] * i1, o[dt][3] * i1, hi1, lo1);
        size_t g0 = (size_t)(b * TT + row0) * (NH * HD) + col;
        size_t g1 = (size_t)(b * TT + row1) * (NH * HD) + col;
        *(uint32_t*)(Ohg + g0) = hi0;
        *(uint32_t*)(Olg + g0) = lo0;
        *(uint32_t*)(Ohg + g1) = hi1;
        *(uint32_t*)(Olg + g1) = lo1;
    }
}

// ---------------------------------------------------------------------------
// Launch
// ---------------------------------------------------------------------------
extern "C" void kernel_launch(void* const* d_in, const int* in_sizes, int n_in,
                              void* d_out, int out_size)
{
    const float* x    = (const float*)d_in[0];
    const float* cosv = (const float*)d_in[1];
    const float* sinv = (const float*)d_in[2];
    const float* Wq   = (const float*)d_in[3];
    const float* Wk   = (const float*)d_in[4];
    const float* Wv   = (const float*)d_in[5];
    const float* Wo   = (const float*)d_in[6];
    float* out = (float*)d_out;

    float *q, *k, *v;
    cudaGetSymbolAddress((void**)&q, g_q);
    cudaGetSymbolAddress((void**)&k, g_k);
    cudaGetSymbolAddress((void**)&v, g_v);

    __nv_bfloat16 *xh, *xl, *wqh, *wql, *wkh, *wkl, *wvh, *wvl, *woh, *wol, *ah, *al;
    __nv_bfloat16 *qsh, *qsl, *ksh, *ksl, *vsh, *vsl;
    cudaGetSymbolAddress((void**)&xh,  g_xh);   cudaGetSymbolAddress((void**)&xl,  g_xl);
    cudaGetSymbolAddress((void**)&wqh, g_wqh);  cudaGetSymbolAddress((void**)&wql, g_wql);
    cudaGetSymbolAddress((void**)&wkh, g_wkh);  cudaGetSymbolAddress((void**)&wkl, g_wkl);
    cudaGetSymbolAddress((void**)&wvh, g_wvh);  cudaGetSymbolAddress((void**)&wvl, g_wvl);
    cudaGetSymbolAddress((void**)&woh, g_woh);  cudaGetSymbolAddress((void**)&wol, g_wol);
    cudaGetSymbolAddress((void**)&ah,  g_ah);   cudaGetSymbolAddress((void**)&al,  g_al);
    cudaGetSymbolAddress((void**)&qsh, g_qsh);  cudaGetSymbolAddress((void**)&qsl, g_qsl);
    cudaGetSymbolAddress((void**)&ksh, g_ksh);  cudaGetSymbolAddress((void**)&ksl, g_ksl);
    cudaGetSymbolAddress((void**)&vsh, g_vsh);  cudaGetSymbolAddress((void**)&vsl, g_vsl);

    cudaFuncSetAttribute(gemm_tc, cudaFuncAttributeMaxDynamicSharedMemorySize, GEMM_SMEM);
    cudaFuncSetAttribute(attn_tc, cudaFuncAttributeMaxDynamicSharedMemorySize, ATTN_SMEM);

    // split conversions (inputs + weights)
    {
        int n;
        n = MROWS * DM;     cvt_split<<<(n+255)/256, 256>>>(x,  xh,  xl,  n);
        n = NH*HD * DM;     cvt_split<<<(n+255)/256, 256>>>(Wq, wqh, wql, n);
        n = NKV*HD * DM;    cvt_split<<<(n+255)/256, 256>>>(Wk, wkh, wkl, n);
        n = NKV*HD * DM;    cvt_split<<<(n+255)/256, 256>>>(Wv, wvh, wvl, n);
        n = DM * NH*HD;     cvt_split<<<(n+255)/256, 256>>>(Wo, woh, wol, n);
    }

    // projections (fp32 out, needed for exact RoPE)
    gemm_tc<<<dim3((NH*HD)/GBN,  MROWS/GBM), 256, GEMM_SMEM>>>(xh, xl, wqh, wql, q, MROWS, NH*HD,  DM);
    gemm_tc<<<dim3((NKV*HD)/GBN, MROWS/GBM), 256, GEMM_SMEM>>>(xh, xl, wkh, wkl, k, MROWS, NKV*HD, DM);
    gemm_tc<<<dim3((NKV*HD)/GBN, MROWS/GBM), 256, GEMM_SMEM>>>(xh, xl, wvh, wvl, v, MROWS, NKV*HD, DM);

    // RoPE fused with split (q pre-scaled by 1/sqrt(hd)); v plain split
    {
        int tq = MROWS * NH * 32;
        rope_split<<<(tq + 255)/256, 256>>>(q, cosv, sinv, qsh, qsl, MROWS*NH, NH, 0.125f);
        int tk = MROWS * NKV * 32;
        rope_split<<<(tk + 255)/256, 256>>>(k, cosv, sinv, ksh, ksl, MROWS*NKV, NKV, 1.0f);
        int nv = MROWS * NKV * HD;
        cvt_split<<<(nv + 255)/256, 256>>>(v, vsh, vsl, nv);
    }

    // tensor-core flash attention -> split bf16 att (g_ah/g_al)
    attn_tc<<<dim3(TT/ATQ, BB*NH), 128, ATTN_SMEM>>>(qsh, qsl, ksh, ksl, vsh, vsl, ah, al);

    // output projection
    gemm_tc<<<dim3(DM/GBN, MROWS/GBM), 256, GEMM_SMEM>>>(ah, al, woh, wol, out, MROWS, DM, DM);
}

// round 9
// speedup vs baseline: 2.8386x; 1.3333x over previous
#include <cuda_runtime.h>
#include <cuda_bf16.h>
#include <math.h>
#include <stdint.h>

// Problem constants
#define BB 2
#define TT 2048
#define DM 2048
#define NH 32
#define NKV 8
#define HD 64
#define MROWS (BB*TT)          // 4096

// ---------------------------------------------------------------------------
// Scratch (device globals — no allocation allowed)
// ---------------------------------------------------------------------------
__device__ float g_q[MROWS * NH * HD];      // fp32 Q projection
__device__ float g_kv[MROWS * 1024];        // fp32 fused K|V projection (cols 0-511 K, 512-1023 V)

// split-bf16 operand buffers
__device__ __align__(16) __nv_bfloat16 g_xh[MROWS * DM];
__device__ __align__(16) __nv_bfloat16 g_xl[MROWS * DM];
__device__ __align__(16) __nv_bfloat16 g_wqh[NH*HD * DM];
__device__ __align__(16) __nv_bfloat16 g_wql[NH*HD * DM];
__device__ __align__(16) __nv_bfloat16 g_wkvh[1024 * DM];   // rows 0-511 Wk, 512-1023 Wv
__device__ __align__(16) __nv_bfloat16 g_wkvl[1024 * DM];
__device__ __align__(16) __nv_bfloat16 g_woh[DM * NH*HD];
__device__ __align__(16) __nv_bfloat16 g_wol[DM * NH*HD];
__device__ __align__(16) __nv_bfloat16 g_ah[MROWS * NH*HD];   // attn out split
__device__ __align__(16) __nv_bfloat16 g_al[MROWS * NH*HD];

// split bf16 q/k/v for attention (post-rope, compact layouts)
__device__ __align__(16) __nv_bfloat16 g_qsh[MROWS * NH * HD];
__device__ __align__(16) __nv_bfloat16 g_qsl[MROWS * NH * HD];
__device__ __align__(16) __nv_bfloat16 g_ksh[MROWS * NKV * HD];
__device__ __align__(16) __nv_bfloat16 g_ksl[MROWS * NKV * HD];
__device__ __align__(16) __nv_bfloat16 g_vsh[MROWS * NKV * HD];
__device__ __align__(16) __nv_bfloat16 g_vsl[MROWS * NKV * HD];

// ---------------------------------------------------------------------------
// mma.sync / cp.async helpers (target-portable)
// ---------------------------------------------------------------------------
__device__ __forceinline__ uint32_t smem_u32(const void* p) {
    uint32_t a;
    asm("{ .reg .u64 t; cvta.to.shared.u64 t, %1; cvt.u32.u64 %0, t; }" : "=r"(a) : "l"(p));
    return a;
}
__device__ __forceinline__ void ldsm_x4(uint32_t* r, uint32_t addr) {
    asm volatile("ldmatrix.sync.aligned.m8n8.x4.shared.b16 {%0,%1,%2,%3}, [%4];"
        : "=r"(r[0]), "=r"(r[1]), "=r"(r[2]), "=r"(r[3]) : "r"(addr));
}
__device__ __forceinline__ void ldsm_x2(uint32_t* r, uint32_t addr) {
    asm volatile("ldmatrix.sync.aligned.m8n8.x2.shared.b16 {%0,%1}, [%2];"
        : "=r"(r[0]), "=r"(r[1]) : "r"(addr));
}
__device__ __forceinline__ void mma16816(float* d, const uint32_t* a, const uint32_t* b) {
    asm volatile("mma.sync.aligned.m16n8k16.row.col.f32.bf16.bf16.f32 "
        "{%0,%1,%2,%3}, {%4,%5,%6,%7}, {%8,%9}, {%0,%1,%2,%3};"
        : "+f"(d[0]), "+f"(d[1]), "+f"(d[2]), "+f"(d[3])
        : "r"(a[0]), "r"(a[1]), "r"(a[2]), "r"(a[3]), "r"(b[0]), "r"(b[1]));
}
__device__ __forceinline__ void cp16(uint32_t dst, const void* src) {
    asm volatile("cp.async.cg.shared.global [%0], [%1], 16;" :: "r"(dst), "l"(src) : "memory");
}
#define CP_COMMIT() asm volatile("cp.async.commit_group;" ::: "memory")
#define CP_WAIT1()  asm volatile("cp.async.wait_group 1;" ::: "memory")
#define CP_WAIT0()  asm volatile("cp.async.wait_group 0;" ::: "memory")

// split x,y into hi/lo bf16x2 packs
__device__ __forceinline__ void split_pack(float x, float y, uint32_t& hi, uint32_t& lo) {
    __nv_bfloat16 hx = __float2bfloat16(x), hy = __float2bfloat16(y);
    float rx = x - __bfloat162float(hx);
    float ry = y - __bfloat162float(hy);
    hi = (uint32_t)(*(uint16_t*)&hx) | ((uint32_t)(*(uint16_t*)&hy) << 16);
    __nv_bfloat16 lx = __float2bfloat16(rx), ly = __float2bfloat16(ry);
    lo = (uint32_t)(*(uint16_t*)&lx) | ((uint32_t)(*(uint16_t*)&ly) << 16);
}

// ---------------------------------------------------------------------------
// Split-bf16 conversion: f = hi + lo
// ---------------------------------------------------------------------------
__global__ void cvt_split(const float* __restrict__ src,
                          __nv_bfloat16* __restrict__ hi,
                          __nv_bfloat16* __restrict__ lo, int n)
{
    int i = blockIdx.x * blockDim.x + threadIdx.x;
    if (i >= n) return;
    float f = src[i];
    __nv_bfloat16 h = __float2bfloat16(f);
    float r = f - __bfloat162float(h);
    hi[i] = h;
    lo[i] = __float2bfloat16(r);
}

// strided variant: pulls V columns (512..1023) out of the fused KV output
__global__ void cvt_splitv(const float* __restrict__ src,
                           __nv_bfloat16* __restrict__ hi,
                           __nv_bfloat16* __restrict__ lo, int n)
{
    int i = blockIdx.x * blockDim.x + threadIdx.x;
    if (i >= n) return;
    int row = i >> 9;            // NKV*HD = 512
    int c   = i & 511;
    float f = src[(size_t)row * 1024 + 512 + c];
    __nv_bfloat16 h = __float2bfloat16(f);
    float r = f - __bfloat162float(h);
    hi[i] = h;
    lo[i] = __float2bfloat16(r);
}

// ---------------------------------------------------------------------------
// Pipelined tensor-core split-bf16 GEMM (NT): C = A * B^T, ~fp32 precision.
// 128x128 CTA tile, BK=32, 256 threads, 2-stage cp.async double buffering.
// ---------------------------------------------------------------------------
#define GBM 128
#define GBN 128
#define GBK 32
#define LDS 40                      // smem row stride in bf16 (32 data + 8 pad)
#define TILE_B (GBM * LDS * 2)      // 10240 B
#define OFF_AH 0
#define OFF_AL (TILE_B)
#define OFF_BH (2*TILE_B)
#define OFF_BL (3*TILE_B)
#define STAGE_B (4*TILE_B)          // 40960 B per stage
#define GEMM_SMEM (2*STAGE_B)       // 81920 B

__global__ __launch_bounds__(256) void gemm_tc(
    const __nv_bfloat16* __restrict__ Ahg, const __nv_bfloat16* __restrict__ Alg,
    const __nv_bfloat16* __restrict__ Bhg, const __nv_bfloat16* __restrict__ Blg,
    float* __restrict__ C, int M, int N, int K)
{
    extern __shared__ char smem[];
    const uint32_t sb = smem_u32(smem);

    const int tid  = threadIdx.x;
    const int wid  = tid >> 5;
    const int lane = tid & 31;
    const int wm   = wid & 1;
    const int wn   = wid >> 1;

    const int brow = blockIdx.y * GBM;
    const int bcol = blockIdx.x * GBN;

    const uint32_t aoff = (uint32_t)((wm*64 + (lane & 15)) * (LDS*2) + (lane >> 4) * 16);
    const uint32_t boff = (uint32_t)((wn*32 + (lane & 7)) * (LDS*2) + ((lane >> 3) & 1) * 16);

    // loader lane mapping (fixed per thread)
    const int lr  = tid >> 2;          // row 0..63 (x2 halves)
    const int lc8 = tid & 3;           // 16B chunk within 64B row data

    float acc[4][4][4];
    #pragma unroll
    for (int mi = 0; mi < 4; mi++)
        #pragma unroll
        for (int ni = 0; ni < 4; ni++)
            #pragma unroll
            for (int r = 0; r < 4; r++) acc[mi][ni][r] = 0.f;

    const int niter = K / GBK;

    // issue loads for one stage
    auto load_stage = [&](int stage, int k0) {
        const uint32_t st = sb + stage * STAGE_B;
        #pragma unroll
        for (int i = 0; i < 2; i++) {
            int r = lr + i * 64;
            size_t ga = (size_t)(brow + r) * K + k0 + lc8 * 8;
            size_t gb = (size_t)(bcol + r) * K + k0 + lc8 * 8;
            uint32_t so = (uint32_t)(r * (LDS*2) + lc8 * 16);
            cp16(st + OFF_AH + so, Ahg + ga);
            cp16(st + OFF_AL + so, Alg + ga);
            cp16(st + OFF_BH + so, Bhg + gb);
            cp16(st + OFF_BL + so, Blg + gb);
        }
    };

    load_stage(0, 0);
    CP_COMMIT();

    for (int it = 0; it < niter; it++) {
        const int buf = it & 1;
        if (it + 1 < niter) {
            load_stage(buf ^ 1, (it + 1) * GBK);
            CP_COMMIT();
            CP_WAIT1();
        } else {
            CP_WAIT0();
        }
        __syncthreads();

        const uint32_t st = sb + buf * STAGE_B;
        #pragma unroll
        for (int kk = 0; kk < GBK; kk += 16) {
            const uint32_t kb = kk * 2;

            uint32_t ah[4][4], bh[4][2];
            #pragma unroll
            for (int mi = 0; mi < 4; mi++)
                ldsm_x4(ah[mi], st + OFF_AH + aoff + mi * 16 * (LDS*2) + kb);
            #pragma unroll
            for (int ni = 0; ni < 4; ni++)
                ldsm_x2(bh[ni], st + OFF_BH + boff + ni * 8 * (LDS*2) + kb);

            #pragma unroll
            for (int mi = 0; mi < 4; mi++)
                #pragma unroll
                for (int ni = 0; ni < 4; ni++)
                    mma16816(acc[mi][ni], ah[mi], bh[ni]);

            {
                uint32_t bl[4][2];
                #pragma unroll
                for (int ni = 0; ni < 4; ni++)
                    ldsm_x2(bl[ni], st + OFF_BL + boff + ni * 8 * (LDS*2) + kb);
                #pragma unroll
                for (int mi = 0; mi < 4; mi++)
                    #pragma unroll
                    for (int ni = 0; ni < 4; ni++)
                        mma16816(acc[mi][ni], ah[mi], bl[ni]);
            }
            {
                uint32_t al[4][4];
                #pragma unroll
                for (int mi = 0; mi < 4; mi++)
                    ldsm_x4(al[mi], st + OFF_AL + aoff + mi * 16 * (LDS*2) + kb);
                #pragma unroll
                for (int mi = 0; mi < 4; mi++)
                    #pragma unroll
                    for (int ni = 0; ni < 4; ni++)
                        mma16816(acc[mi][ni], al[mi], bh[ni]);
            }
        }
        __syncthreads();   // protect this buf from being overwritten by load(it+2)
    }

    const int er = lane >> 2;
    const int ec = (lane & 3) * 2;
    #pragma unroll
    for (int mi = 0; mi < 4; mi++) {
        #pragma unroll
        for (int ni = 0; ni < 4; ni++) {
            int row = brow + wm*64 + mi*16 + er;
            int col = bcol + wn*32 + ni*8 + ec;
            float2* p0 = (float2*)(C + (size_t)row * N + col);
            float2* p1 = (float2*)(C + (size_t)(row + 8) * N + col);
            *p0 = make_float2(acc[mi][ni][0], acc[mi][ni][1]);
            *p1 = make_float2(acc[mi][ni][2], acc[mi][ni][3]);
        }
    }
}

// ---------------------------------------------------------------------------
// RoPE fused with bf16 split. src has row stride srcStride; head h at col h*HD.
// ---------------------------------------------------------------------------
__global__ void rope_split(const float* __restrict__ src,
                           const float* __restrict__ cost,
                           const float* __restrict__ sint,
                           __nv_bfloat16* __restrict__ dh,
                           __nv_bfloat16* __restrict__ dl,
                           int rowsHeads, int nh, int srcStride, float scale)
{
    int idx = blockIdx.x * blockDim.x + threadIdx.x;
    int total = rowsHeads * 32;
    if (idx >= total) return;
    int d  = idx & 31;
    int rh = idx >> 5;
    int bt = rh / nh;
    int h  = rh - bt * nh;
    int t  = bt & (TT - 1);
    float c = cost[t * HD + d];
    float s = sint[t * HD + d];
    const float* base = src + (size_t)bt * srcStride + h * HD;
    float x1 = base[d];
    float x2 = base[d + 32];
    float y1 = fmaf(x1, c, -x2 * s) * scale;
    float y2 = fmaf(x2, c,  x1 * s) * scale;
    size_t o = (size_t)rh * HD;
    __nv_bfloat16 h1 = __float2bfloat16(y1);
    __nv_bfloat16 h2 = __float2bfloat16(y2);
    dh[o + d]      = h1;
    dh[o + d + 32] = h2;
    dl[o + d]      = __float2bfloat16(y1 - __bfloat162float(h1));
    dl[o + d + 32] = __float2bfloat16(y2 - __bfloat162float(h2));
}

// ---------------------------------------------------------------------------
// Flash attention on mma.sync, split-bf16 QK and PV (unchanged from R8 pass)
// ---------------------------------------------------------------------------
#define ATQ 64
#define ATK 64
#define ASTR   72
#define ASTRB  144
#define S_QH 0
#define S_QL (64*ASTRB)
#define S_KH (2*64*ASTRB)
#define S_KL (3*64*ASTRB)
#define S_VH (4*64*ASTRB)
#define S_VL (5*64*ASTRB)
#define ATTN_SMEM (6*64*ASTRB)

__global__ __launch_bounds__(128) void attn_tc(
    const __nv_bfloat16* __restrict__ qsh, const __nv_bfloat16* __restrict__ qsl,
    const __nv_bfloat16* __restrict__ ksh, const __nv_bfloat16* __restrict__ ksl,
    const __nv_bfloat16* __restrict__ vsh, const __nv_bfloat16* __restrict__ vsl,
    __nv_bfloat16* __restrict__ Ohg, __nv_bfloat16* __restrict__ Olg)
{
    extern __shared__ char smem[];
    const uint32_t sb = smem_u32(smem);
    const int tid  = threadIdx.x;
    const int wid  = tid >> 5;
    const int lane = tid & 31;

    const int qt = blockIdx.x;
    const int bh = blockIdx.y;
    const int b  = bh >> 5;
    const int h  = bh & 31;
    const int kv = h >> 2;
    const int q0 = qt * ATQ;

    #pragma unroll
    for (int i = 0; i < 4; i++) {
        int idx = tid + i * 128;
        int r   = idx >> 3;
        int c8  = idx & 7;
        size_t g = ((size_t)(b * TT + q0 + r) * NH + h) * HD + c8 * 8;
        uint32_t so = (uint32_t)(r * ASTRB + c8 * 16);
        *(uint4*)(smem + S_QH + so) = *(const uint4*)(qsh + g);
        *(uint4*)(smem + S_QL + so) = *(const uint4*)(qsl + g);
    }
    __syncthreads();

    uint32_t qh[4][4], ql[4][4];
    {
        uint32_t abase = (uint32_t)((wid*16 + (lane & 15)) * ASTRB + (lane >> 4) * 16);
        #pragma unroll
        for (int ks = 0; ks < 4; ks++) {
            ldsm_x4(qh[ks], sb + S_QH + abase + ks * 32);
            ldsm_x4(ql[ks], sb + S_QL + abase + ks * 32);
        }
    }

    float o[8][4];
    #pragma unroll
    for (int dt = 0; dt < 8; dt++)
        #pragma unroll
        for (int r = 0; r < 4; r++) o[dt][r] = 0.f;
    float m0 = -1e30f, m1 = -1e30f, l0 = 0.f, l1 = 0.f;

    const int ntiles = qt + 1;
    const uint32_t bbase = (uint32_t)((lane & 7) * ASTRB + ((lane >> 3) & 1) * 16);

    for (int kt = 0; kt < ntiles; kt++) {
        const int k0 = kt * ATK;
        __syncthreads();

        #pragma unroll
        for (int i = 0; i < 4; i++) {
            int idx = tid + i * 128;
            int r   = idx >> 3;
            int c8  = idx & 7;
            size_t g = ((size_t)(b * TT + k0 + r) * NKV + kv) * HD + c8 * 8;
            uint32_t so = (uint32_t)(r * ASTRB + c8 * 16);
            *(uint4*)(smem + S_KH + so) = *(const uint4*)(ksh + g);
            *(uint4*)(smem + S_KL + so) = *(const uint4*)(ksl + g);
        }
        #pragma unroll
        for (int i = 0; i < 4; i++) {
            int idx = tid + i * 128;
            int r   = idx >> 3;
            int d0  = (idx & 7) * 8;
            size_t g = ((size_t)(b * TT + k0 + r) * NKV + kv) * HD + d0;
            uint4 vh4 = *(const uint4*)(vsh + g);
            uint4 vl4 = *(const uint4*)(vsl + g);
            const __nv_bfloat16* ph = (const __nv_bfloat16*)&vh4;
            const __nv_bfloat16* pl = (const __nv_bfloat16*)&vl4;
            #pragma unroll
            for (int e = 0; e < 8; e++) {
                *(__nv_bfloat16*)(smem + S_VH + (d0 + e) * ASTRB + r * 2) = ph[e];
                *(__nv_bfloat16*)(smem + S_VL + (d0 + e) * ASTRB + r * 2) = pl[e];
            }
        }
        __syncthreads();

        float s[8][4];
        #pragma unroll
        for (int nt = 0; nt < 8; nt++)
            #pragma unroll
            for (int r = 0; r < 4; r++) s[nt][r] = 0.f;

        #pragma unroll
        for (int ks = 0; ks < 4; ks++) {
            #pragma unroll
            for (int nt = 0; nt < 8; nt++) {
                uint32_t kh2[2], kl2[2];
                uint32_t ka = sb + bbase + nt * 8 * ASTRB + ks * 32;
                ldsm_x2(kh2, S_KH + ka);
                ldsm_x2(kl2, S_KL + ka);
                mma16816(s[nt], qh[ks], kh2);
                mma16816(s[nt], qh[ks], kl2);
                mma16816(s[nt], ql[ks], kh2);
            }
        }

        const int row0 = q0 + wid * 16 + (lane >> 2);
        const int row1 = row0 + 8;
        if (kt == qt) {
            #pragma unroll
            for (int nt = 0; nt < 8; nt++) {
                int col = k0 + nt * 8 + (lane & 3) * 2;
                if (col     > row0) s[nt][0] = -1e30f;
                if (col + 1 > row0) s[nt][1] = -1e30f;
                if (col     > row1) s[nt][2] = -1e30f;
                if (col + 1 > row1) s[nt][3] = -1e30f;
            }
        }

        float mx0 = m0, mx1 = m1;
        #pragma unroll
        for (int nt = 0; nt < 8; nt++) {
            mx0 = fmaxf(mx0, fmaxf(s[nt][0], s[nt][1]));
            mx1 = fmaxf(mx1, fmaxf(s[nt][2], s[nt][3]));
        }
        mx0 = fmaxf(mx0, __shfl_xor_sync(0xFFFFFFFF, mx0, 1));
        mx0 = fmaxf(mx0, __shfl_xor_sync(0xFFFFFFFF, mx0, 2));
        mx1 = fmaxf(mx1, __shfl_xor_sync(0xFFFFFFFF, mx1, 1));
        mx1 = fmaxf(mx1, __shfl_xor_sync(0xFFFFFFFF, mx1, 2));

        float c0 = __expf(m0 - mx0);
        float c1 = __expf(m1 - mx1);
        m0 = mx0; m1 = mx1;
        l0 *= c0;  l1 *= c1;
        #pragma unroll
        for (int dt = 0; dt < 8; dt++) {
            o[dt][0] *= c0; o[dt][1] *= c0;
            o[dt][2] *= c1; o[dt][3] *= c1;
        }

        uint32_t pha[4][4], pla[4][4];
        float rs0 = 0.f, rs1 = 0.f;
        #pragma unroll
        for (int j = 0; j < 8; j++) {
            float p0 = __expf(s[j][0] - m0);
            float p1 = __expf(s[j][1] - m0);
            float p2 = __expf(s[j][2] - m1);
            float p3 = __expf(s[j][3] - m1);
            rs0 += p0 + p1;
            rs1 += p2 + p3;
            uint32_t hi01, lo01, hi23, lo23;
            split_pack(p0, p1, hi01, lo01);
            split_pack(p2, p3, hi23, lo23);
            int c = j >> 1;
            if ((j & 1) == 0) {
                pha[c][0] = hi01; pla[c][0] = lo01;
                pha[c][1] = hi23; pla[c][1] = lo23;
            } else {
                pha[c][2] = hi01; pla[c][2] = lo01;
                pha[c][3] = hi23; pla[c][3] = lo23;
            }
        }
        rs0 += __shfl_xor_sync(0xFFFFFFFF, rs0, 1);
        rs0 += __shfl_xor_sync(0xFFFFFFFF, rs0, 2);
        rs1 += __shfl_xor_sync(0xFFFFFFFF, rs1, 1);
        rs1 += __shfl_xor_sync(0xFFFFFFFF, rs1, 2);
        l0 += rs0;
        l1 += rs1;

        #pragma unroll
        for (int ks = 0; ks < 4; ks++) {
            #pragma unroll
            for (int dt = 0; dt < 8; dt++) {
                uint32_t vh2[2], vl2[2];
                uint32_t va = sb + bbase + dt * 8 * ASTRB + ks * 32;
                ldsm_x2(vh2, S_VH + va);
                ldsm_x2(vl2, S_VL + va);
                mma16816(o[dt], pha[ks], vh2);
                mma16816(o[dt], pha[ks], vl2);
                mma16816(o[dt], pla[ks], vh2);
            }
        }
    }

    const float i0 = 1.f / l0;
    const float i1 = 1.f / l1;
    const int row0 = q0 + wid * 16 + (lane >> 2);
    const int row1 = row0 + 8;
    const int colb = h * HD + (lane & 3) * 2;
    #pragma unroll
    for (int dt = 0; dt < 8; dt++) {
        int col = colb + dt * 8;
        uint32_t hi0, lo0, hi1, lo1;
        split_pack(o[dt][0] * i0, o[dt][1] * i0, hi0, lo0);
        split_pack(o[dt][2] * i1, o[dt][3] * i1, hi1, lo1);
        size_t g0 = (size_t)(b * TT + row0) * (NH * HD) + col;
        size_t g1 = (size_t)(b * TT + row1) * (NH * HD) + col;
        *(uint32_t*)(Ohg + g0) = hi0;
        *(uint32_t*)(Olg + g0) = lo0;
        *(uint32_t*)(Ohg + g1) = hi1;
        *(uint32_t*)(Olg + g1) = lo1;
    }
}

// ---------------------------------------------------------------------------
// Launch
// ---------------------------------------------------------------------------
extern "C" void kernel_launch(void* const* d_in, const int* in_sizes, int n_in,
                              void* d_out, int out_size)
{
    const float* x    = (const float*)d_in[0];
    const float* cosv = (const float*)d_in[1];
    const float* sinv = (const float*)d_in[2];
    const float* Wq   = (const float*)d_in[3];
    const float* Wk   = (const float*)d_in[4];
    const float* Wv   = (const float*)d_in[5];
    const float* Wo   = (const float*)d_in[6];
    float* out = (float*)d_out;

    float *q, *kvb;
    cudaGetSymbolAddress((void**)&q,   g_q);
    cudaGetSymbolAddress((void**)&kvb, g_kv);

    __nv_bfloat16 *xh, *xl, *wqh, *wql, *wkvh, *wkvl, *woh, *wol, *ah, *al;
    __nv_bfloat16 *qsh, *qsl, *ksh, *ksl, *vsh, *vsl;
    cudaGetSymbolAddress((void**)&xh,   g_xh);    cudaGetSymbolAddress((void**)&xl,   g_xl);
    cudaGetSymbolAddress((void**)&wqh,  g_wqh);   cudaGetSymbolAddress((void**)&wql,  g_wql);
    cudaGetSymbolAddress((void**)&wkvh, g_wkvh);  cudaGetSymbolAddress((void**)&wkvl, g_wkvl);
    cudaGetSymbolAddress((void**)&woh,  g_woh);   cudaGetSymbolAddress((void**)&wol,  g_wol);
    cudaGetSymbolAddress((void**)&ah,   g_ah);    cudaGetSymbolAddress((void**)&al,   g_al);
    cudaGetSymbolAddress((void**)&qsh,  g_qsh);   cudaGetSymbolAddress((void**)&qsl,  g_qsl);
    cudaGetSymbolAddress((void**)&ksh,  g_ksh);   cudaGetSymbolAddress((void**)&ksl,  g_ksl);
    cudaGetSymbolAddress((void**)&vsh,  g_vsh);   cudaGetSymbolAddress((void**)&vsl,  g_vsl);

    cudaFuncSetAttribute(gemm_tc, cudaFuncAttributeMaxDynamicSharedMemorySize, GEMM_SMEM);
    cudaFuncSetAttribute(attn_tc, cudaFuncAttributeMaxDynamicSharedMemorySize, ATTN_SMEM);

    // split conversions (inputs + weights; Wk|Wv concatenated along N)
    {
        int n;
        n = MROWS * DM;     cvt_split<<<(n+255)/256, 256>>>(x,  xh,  xl,  n);
        n = NH*HD * DM;     cvt_split<<<(n+255)/256, 256>>>(Wq, wqh, wql, n);
        n = NKV*HD * DM;    cvt_split<<<(n+255)/256, 256>>>(Wk, wkvh, wkvl, n);
        n = NKV*HD * DM;    cvt_split<<<(n+255)/256, 256>>>(Wv, wkvh + (size_t)512*DM, wkvl + (size_t)512*DM, n);
        n = DM * NH*HD;     cvt_split<<<(n+255)/256, 256>>>(Wo, woh, wol, n);
    }

    // projections: Q (N=2048) and fused K|V (N=1024)
    gemm_tc<<<dim3((NH*HD)/GBN, MROWS/GBM), 256, GEMM_SMEM>>>(xh, xl, wqh,  wql,  q,   MROWS, NH*HD, DM);
    gemm_tc<<<dim3(1024/GBN,    MROWS/GBM), 256, GEMM_SMEM>>>(xh, xl, wkvh, wkvl, kvb, MROWS, 1024,  DM);

    // RoPE fused with split (q pre-scaled by 1/8); v strided split
    {
        int tq = MROWS * NH * 32;
        rope_split<<<(tq + 255)/256, 256>>>(q, cosv, sinv, qsh, qsl, MROWS*NH, NH, NH*HD, 0.125f);
        int tk = MROWS * NKV * 32;
        rope_split<<<(tk + 255)/256, 256>>>(kvb, cosv, sinv, ksh, ksl, MROWS*NKV, NKV, 1024, 1.0f);
        int nv = MROWS * NKV * HD;
        cvt_splitv<<<(nv + 255)/256, 256>>>(kvb, vsh, vsl, nv);
    }

    // tensor-core flash attention -> split bf16 att
    attn_tc<<<dim3(TT/ATQ, BB*NH), 128, ATTN_SMEM>>>(qsh, qsl, ksh, ksl, vsh, vsl, ah, al);

    // output projection
    gemm_tc<<<dim3(DM/GBN, MROWS/GBM), 256, GEMM_SMEM>>>(ah, al, woh, wol, out, MROWS, DM, DM);
}

// round 10
// speedup vs baseline: 3.2057x; 1.1293x over previous
#include <cuda_runtime.h>
#include <cuda_bf16.h>
#include <math.h>
#include <stdint.h>

// Problem constants
#define BB 2
#define TT 2048
#define DM 2048
#define NH 32
#define NKV 8
#define HD 64
#define MROWS (BB*TT)          // 4096

// ---------------------------------------------------------------------------
// Scratch (device globals — no allocation allowed)
// ---------------------------------------------------------------------------
__device__ float g_qkv[MROWS * 3072];       // fused Q|K|V fp32 (cols: 0-2047 Q, 2048-2559 K, 2560-3071 V)

// split-bf16 operand buffers
__device__ __align__(16) __nv_bfloat16 g_xh[MROWS * DM];
__device__ __align__(16) __nv_bfloat16 g_xl[MROWS * DM];
__device__ __align__(16) __nv_bfloat16 g_wqkvh[3072 * DM];  // rows: 0-2047 Wq, 2048-2559 Wk, 2560-3071 Wv
__device__ __align__(16) __nv_bfloat16 g_wqkvl[3072 * DM];
__device__ __align__(16) __nv_bfloat16 g_woh[DM * NH*HD];
__device__ __align__(16) __nv_bfloat16 g_wol[DM * NH*HD];
__device__ __align__(16) __nv_bfloat16 g_ah[MROWS * NH*HD];   // attn out split
__device__ __align__(16) __nv_bfloat16 g_al[MROWS * NH*HD];

// split bf16 q/k/v for attention (post-rope, compact layouts)
__device__ __align__(16) __nv_bfloat16 g_qsh[MROWS * NH * HD];
__device__ __align__(16) __nv_bfloat16 g_qsl[MROWS * NH * HD];
__device__ __align__(16) __nv_bfloat16 g_ksh[MROWS * NKV * HD];
__device__ __align__(16) __nv_bfloat16 g_ksl[MROWS * NKV * HD];
__device__ __align__(16) __nv_bfloat16 g_vsh[MROWS * NKV * HD];
__device__ __align__(16) __nv_bfloat16 g_vsl[MROWS * NKV * HD];

// ---------------------------------------------------------------------------
// mma.sync / cp.async helpers (target-portable)
// ---------------------------------------------------------------------------
__device__ __forceinline__ uint32_t smem_u32(const void* p) {
    uint32_t a;
    asm("{ .reg .u64 t; cvta.to.shared.u64 t, %1; cvt.u32.u64 %0, t; }" : "=r"(a) : "l"(p));
    return a;
}
__device__ __forceinline__ void ldsm_x4(uint32_t* r, uint32_t addr) {
    asm volatile("ldmatrix.sync.aligned.m8n8.x4.shared.b16 {%0,%1,%2,%3}, [%4];"
        : "=r"(r[0]), "=r"(r[1]), "=r"(r[2]), "=r"(r[3]) : "r"(addr));
}
__device__ __forceinline__ void ldsm_x4t(uint32_t* r, uint32_t addr) {
    asm volatile("ldmatrix.sync.aligned.m8n8.x4.trans.shared.b16 {%0,%1,%2,%3}, [%4];"
        : "=r"(r[0]), "=r"(r[1]), "=r"(r[2]), "=r"(r[3]) : "r"(addr));
}
__device__ __forceinline__ void ldsm_x2(uint32_t* r, uint32_t addr) {
    asm volatile("ldmatrix.sync.aligned.m8n8.x2.shared.b16 {%0,%1}, [%2];"
        : "=r"(r[0]), "=r"(r[1]) : "r"(addr));
}
__device__ __forceinline__ void mma16816(float* d, const uint32_t* a, const uint32_t* b) {
    asm volatile("mma.sync.aligned.m16n8k16.row.col.f32.bf16.bf16.f32 "
        "{%0,%1,%2,%3}, {%4,%5,%6,%7}, {%8,%9}, {%0,%1,%2,%3};"
        : "+f"(d[0]), "+f"(d[1]), "+f"(d[2]), "+f"(d[3])
        : "r"(a[0]), "r"(a[1]), "r"(a[2]), "r"(a[3]), "r"(b[0]), "r"(b[1]));
}
__device__ __forceinline__ void cp16(uint32_t dst, const void* src) {
    asm volatile("cp.async.cg.shared.global [%0], [%1], 16;" :: "r"(dst), "l"(src) : "memory");
}
#define CP_COMMIT() asm volatile("cp.async.commit_group;" ::: "memory")
#define CP_WAIT1()  asm volatile("cp.async.wait_group 1;" ::: "memory")
#define CP_WAIT0()  asm volatile("cp.async.wait_group 0;" ::: "memory")

// split x,y into hi/lo bf16x2 packs
__device__ __forceinline__ void split_pack(float x, float y, uint32_t& hi, uint32_t& lo) {
    __nv_bfloat16 hx = __float2bfloat16(x), hy = __float2bfloat16(y);
    float rx = x - __bfloat162float(hx);
    float ry = y - __bfloat162float(hy);
    hi = (uint32_t)(*(uint16_t*)&hx) | ((uint32_t)(*(uint16_t*)&hy) << 16);
    __nv_bfloat16 lx = __float2bfloat16(rx), ly = __float2bfloat16(ry);
    lo = (uint32_t)(*(uint16_t*)&lx) | ((uint32_t)(*(uint16_t*)&ly) << 16);
}

// ---------------------------------------------------------------------------
// Split-bf16 conversion: f = hi + lo
// ---------------------------------------------------------------------------
__global__ void cvt_split(const float* __restrict__ src,
                          __nv_bfloat16* __restrict__ hi,
                          __nv_bfloat16* __restrict__ lo, int n)
{
    int i = blockIdx.x * blockDim.x + threadIdx.x;
    if (i >= n) return;
    float f = src[i];
    __nv_bfloat16 h = __float2bfloat16(f);
    float r = f - __bfloat162float(h);
    hi[i] = h;
    lo[i] = __float2bfloat16(r);
}

// strided variant: pulls V columns (2560..3071) out of the fused QKV output
__global__ void cvt_splitv(const float* __restrict__ src,
                           __nv_bfloat16* __restrict__ hi,
                           __nv_bfloat16* __restrict__ lo, int n)
{
    int i = blockIdx.x * blockDim.x + threadIdx.x;
    if (i >= n) return;
    int row = i >> 9;            // NKV*HD = 512
    int c   = i & 511;
    float f = src[(size_t)row * 3072 + 2560 + c];
    __nv_bfloat16 h = __float2bfloat16(f);
    float r = f - __bfloat162float(h);
    hi[i] = h;
    lo[i] = __float2bfloat16(r);
}

// ---------------------------------------------------------------------------
// Pipelined tensor-core split-bf16 GEMM (NT) — unchanged from R9 (passing)
// ---------------------------------------------------------------------------
#define GBM 128
#define GBN 128
#define GBK 32
#define LDS 40
#define TILE_B (GBM * LDS * 2)
#define OFF_AH 0
#define OFF_AL (TILE_B)
#define OFF_BH (2*TILE_B)
#define OFF_BL (3*TILE_B)
#define STAGE_B (4*TILE_B)
#define GEMM_SMEM (2*STAGE_B)

__global__ __launch_bounds__(256) void gemm_tc(
    const __nv_bfloat16* __restrict__ Ahg, const __nv_bfloat16* __restrict__ Alg,
    const __nv_bfloat16* __restrict__ Bhg, const __nv_bfloat16* __restrict__ Blg,
    float* __restrict__ C, int M, int N, int K)
{
    extern __shared__ char smem[];
    const uint32_t sb = smem_u32(smem);

    const int tid  = threadIdx.x;
    const int wid  = tid >> 5;
    const int lane = tid & 31;
    const int wm   = wid & 1;
    const int wn   = wid >> 1;

    const int brow = blockIdx.y * GBM;
    const int bcol = blockIdx.x * GBN;

    const uint32_t aoff = (uint32_t)((wm*64 + (lane & 15)) * (LDS*2) + (lane >> 4) * 16);
    const uint32_t boff = (uint32_t)((wn*32 + (lane & 7)) * (LDS*2) + ((lane >> 3) & 1) * 16);

    const int lr  = tid >> 2;
    const int lc8 = tid & 3;

    float acc[4][4][4];
    #pragma unroll
    for (int mi = 0; mi < 4; mi++)
        #pragma unroll
        for (int ni = 0; ni < 4; ni++)
            #pragma unroll
            for (int r = 0; r < 4; r++) acc[mi][ni][r] = 0.f;

    const int niter = K / GBK;

    auto load_stage = [&](int stage, int k0) {
        const uint32_t st = sb + stage * STAGE_B;
        #pragma unroll
        for (int i = 0; i < 2; i++) {
            int r = lr + i * 64;
            size_t ga = (size_t)(brow + r) * K + k0 + lc8 * 8;
            size_t gb = (size_t)(bcol + r) * K + k0 + lc8 * 8;
            uint32_t so = (uint32_t)(r * (LDS*2) + lc8 * 16);
            cp16(st + OFF_AH + so, Ahg + ga);
            cp16(st + OFF_AL + so, Alg + ga);
            cp16(st + OFF_BH + so, Bhg + gb);
            cp16(st + OFF_BL + so, Blg + gb);
        }
    };

    load_stage(0, 0);
    CP_COMMIT();

    for (int it = 0; it < niter; it++) {
        const int buf = it & 1;
        if (it + 1 < niter) {
            load_stage(buf ^ 1, (it + 1) * GBK);
            CP_COMMIT();
            CP_WAIT1();
        } else {
            CP_WAIT0();
        }
        __syncthreads();

        const uint32_t st = sb + buf * STAGE_B;
        #pragma unroll
        for (int kk = 0; kk < GBK; kk += 16) {
            const uint32_t kb = kk * 2;

            uint32_t ah[4][4], bh[4][2];
            #pragma unroll
            for (int mi = 0; mi < 4; mi++)
                ldsm_x4(ah[mi], st + OFF_AH + aoff + mi * 16 * (LDS*2) + kb);
            #pragma unroll
            for (int ni = 0; ni < 4; ni++)
                ldsm_x2(bh[ni], st + OFF_BH + boff + ni * 8 * (LDS*2) + kb);

            #pragma unroll
            for (int mi = 0; mi < 4; mi++)
                #pragma unroll
                for (int ni = 0; ni < 4; ni++)
                    mma16816(acc[mi][ni], ah[mi], bh[ni]);

            {
                uint32_t bl[4][2];
                #pragma unroll
                for (int ni = 0; ni < 4; ni++)
                    ldsm_x2(bl[ni], st + OFF_BL + boff + ni * 8 * (LDS*2) + kb);
                #pragma unroll
                for (int mi = 0; mi < 4; mi++)
                    #pragma unroll
                    for (int ni = 0; ni < 4; ni++)
                        mma16816(acc[mi][ni], ah[mi], bl[ni]);
            }
            {
                uint32_t al[4][4];
                #pragma unroll
                for (int mi = 0; mi < 4; mi++)
                    ldsm_x4(al[mi], st + OFF_AL + aoff + mi * 16 * (LDS*2) + kb);
                #pragma unroll
                for (int mi = 0; mi < 4; mi++)
                    #pragma unroll
                    for (int ni = 0; ni < 4; ni++)
                        mma16816(acc[mi][ni], al[mi], bh[ni]);
            }
        }
        __syncthreads();
    }

    const int er = lane >> 2;
    const int ec = (lane & 3) * 2;
    #pragma unroll
    for (int mi = 0; mi < 4; mi++) {
        #pragma unroll
        for (int ni = 0; ni < 4; ni++) {
            int row = brow + wm*64 + mi*16 + er;
            int col = bcol + wn*32 + ni*8 + ec;
            float2* p0 = (float2*)(C + (size_t)row * N + col);
            float2* p1 = (float2*)(C + (size_t)(row + 8) * N + col);
            *p0 = make_float2(acc[mi][ni][0], acc[mi][ni][1]);
            *p1 = make_float2(acc[mi][ni][2], acc[mi][ni][3]);
        }
    }
}

// ---------------------------------------------------------------------------
// RoPE fused with bf16 split. src has row stride srcStride; head h at col h*HD.
// ---------------------------------------------------------------------------
__global__ void rope_split(const float* __restrict__ src,
                           const float* __restrict__ cost,
                           const float* __restrict__ sint,
                           __nv_bfloat16* __restrict__ dh,
                           __nv_bfloat16* __restrict__ dl,
                           int rowsHeads, int nh, int srcStride, float scale)
{
    int idx = blockIdx.x * blockDim.x + threadIdx.x;
    int total = rowsHeads * 32;
    if (idx >= total) return;
    int d  = idx & 31;
    int rh = idx >> 5;
    int bt = rh / nh;
    int h  = rh - bt * nh;
    int t  = bt & (TT - 1);
    float c = cost[t * HD + d];
    float s = sint[t * HD + d];
    const float* base = src + (size_t)bt * srcStride + h * HD;
    float x1 = base[d];
    float x2 = base[d + 32];
    float y1 = fmaf(x1, c, -x2 * s) * scale;
    float y2 = fmaf(x2, c,  x1 * s) * scale;
    size_t o = (size_t)rh * HD;
    __nv_bfloat16 h1 = __float2bfloat16(y1);
    __nv_bfloat16 h2 = __float2bfloat16(y2);
    dh[o + d]      = h1;
    dh[o + d + 32] = h2;
    dl[o + d]      = __float2bfloat16(y1 - __bfloat162float(h1));
    dl[o + d + 32] = __float2bfloat16(y2 - __bfloat162float(h2));
}

// ---------------------------------------------------------------------------
// Flash attention v2: split-bf16 mma.sync, x4 ldmatrix, ldsm.trans for V,
// cp.async double-buffered KV tiles.
// CTA: 128 threads (4 warps), Q tile 64 rows, KV tiles 64.
// K and V both stored row-major [kv][d] in smem.
// ---------------------------------------------------------------------------
#define ATQ 64
#define ATK 64
#define ASTRB  144       // 72 bf16 per row (64 data + 8 pad)
#define SQ_H 0
#define SQ_L 9216
#define SST_BASE 18432
#define SST_SZ   36864   // per stage: KH,KL,VH,VL each 9216
#define SK_H 0
#define SK_L 9216
#define SV_H 18432
#define SV_L 27648
#define ATTN_SMEM (SST_BASE + 2*SST_SZ)   // 92160 B

__global__ __launch_bounds__(128) void attn_tc(
    const __nv_bfloat16* __restrict__ qsh, const __nv_bfloat16* __restrict__ qsl,
    const __nv_bfloat16* __restrict__ ksh, const __nv_bfloat16* __restrict__ ksl,
    const __nv_bfloat16* __restrict__ vsh, const __nv_bfloat16* __restrict__ vsl,
    __nv_bfloat16* __restrict__ Ohg, __nv_bfloat16* __restrict__ Olg)
{
    extern __shared__ char smem[];
    const uint32_t sb = smem_u32(smem);
    const int tid  = threadIdx.x;
    const int wid  = tid >> 5;
    const int lane = tid & 31;

    const int qt = blockIdx.x;
    const int bh = blockIdx.y;
    const int b  = bh >> 5;
    const int h  = bh & 31;
    const int kv = h >> 2;
    const int q0 = qt * ATQ;
    const int ntiles = qt + 1;

    // loader mapping
    const int lrr = tid >> 3;        // row/2 pieces: idx>>3 over 4 iters
    const int lc8 = tid & 7;

    // KV tile loader (cp.async)
    auto load_kv = [&](int stage, int k0) {
        const uint32_t st = sb + SST_BASE + stage * SST_SZ;
        #pragma unroll
        for (int i = 0; i < 4; i++) {
            int r = lrr + i * 16;
            size_t g = ((size_t)(b * TT + k0 + r) * NKV + kv) * HD + lc8 * 8;
            uint32_t so = (uint32_t)(r * ASTRB + lc8 * 16);
            cp16(st + SK_H + so, ksh + g);
            cp16(st + SK_L + so, ksl + g);
            cp16(st + SV_H + so, vsh + g);
            cp16(st + SV_L + so, vsl + g);
        }
    };

    // ---- load Q tile (64x64) split into smem ----
    #pragma unroll
    for (int i = 0; i < 4; i++) {
        int r = lrr + i * 16;
        size_t g = ((size_t)(b * TT + q0 + r) * NH + h) * HD + lc8 * 8;
        uint32_t so = (uint32_t)(r * ASTRB + lc8 * 16);
        *(uint4*)(smem + SQ_H + so) = *(const uint4*)(qsh + g);
        *(uint4*)(smem + SQ_L + so) = *(const uint4*)(qsl + g);
    }

    // prefetch first KV tile
    load_kv(0, 0);
    CP_COMMIT();

    __syncthreads();  // Q smem ready

    // ---- per-warp Q fragments ----
    uint32_t qh[4][4], ql[4][4];
    {
        uint32_t abase = (uint32_t)((wid*16 + (lane & 15)) * ASTRB + (lane >> 4) * 16);
        #pragma unroll
        for (int ks = 0; ks < 4; ks++) {
            ldsm_x4(qh[ks], sb + SQ_H + abase + ks * 32);
            ldsm_x4(ql[ks], sb + SQ_L + abase + ks * 32);
        }
    }

    float o[8][4];
    #pragma unroll
    for (int dt = 0; dt < 8; dt++)
        #pragma unroll
        for (int r = 0; r < 4; r++) o[dt][r] = 0.f;
    float m0 = -1e30f, m1 = -1e30f, l0 = 0.f, l1 = 0.f;

    // fragment base (shared by K non-trans x4 and V trans x4)
    const uint32_t fb = (uint32_t)((lane & 15) * ASTRB + (lane >> 4) * 16);

    for (int kt = 0; kt < ntiles; kt++) {
        const int k0 = kt * ATK;
        if (kt + 1 < ntiles) {
            load_kv((kt + 1) & 1, k0 + ATK);
            CP_COMMIT();
            CP_WAIT1();
        } else {
            CP_WAIT0();
        }
        __syncthreads();

        const uint32_t st = sb + SST_BASE + (kt & 1) * SST_SZ;

        // ---- S = Q K^T, split 3-pass, x4 B loads ----
        float s[8][4];
        #pragma unroll
        for (int nt = 0; nt < 8; nt++)
            #pragma unroll
            for (int r = 0; r < 4; r++) s[nt][r] = 0.f;

        #pragma unroll
        for (int ks = 0; ks < 4; ks++) {
            #pragma unroll
            for (int np = 0; np < 4; np++) {
                uint32_t th[4], tl[4];
                uint32_t ka = st + fb + np * (16 * ASTRB) + ks * 32;
                ldsm_x4(th, SK_H + ka);
                ldsm_x4(tl, SK_L + ka);
                uint32_t bh0[2] = {th[0], th[2]}, bh1[2] = {th[1], th[3]};
                uint32_t bl0[2] = {tl[0], tl[2]}, bl1[2] = {tl[1], tl[3]};
                mma16816(s[2*np],   qh[ks], bh0);
                mma16816(s[2*np],   qh[ks], bl0);
                mma16816(s[2*np],   ql[ks], bh0);
                mma16816(s[2*np+1], qh[ks], bh1);
                mma16816(s[2*np+1], qh[ks], bl1);
                mma16816(s[2*np+1], ql[ks], bh1);
            }
        }

        // ---- causal mask (diagonal tile only) ----
        const int row0 = q0 + wid * 16 + (lane >> 2);
        const int row1 = row0 + 8;
        if (kt == qt) {
            #pragma unroll
            for (int nt = 0; nt < 8; nt++) {
                int col = k0 + nt * 8 + (lane & 3) * 2;
                if (col     > row0) s[nt][0] = -1e30f;
                if (col + 1 > row0) s[nt][1] = -1e30f;
                if (col     > row1) s[nt][2] = -1e30f;
                if (col + 1 > row1) s[nt][3] = -1e30f;
            }
        }

        // ---- online softmax ----
        float mx0 = m0, mx1 = m1;
        #pragma unroll
        for (int nt = 0; nt < 8; nt++) {
            mx0 = fmaxf(mx0, fmaxf(s[nt][0], s[nt][1]));
            mx1 = fmaxf(mx1, fmaxf(s[nt][2], s[nt][3]));
        }
        mx0 = fmaxf(mx0, __shfl_xor_sync(0xFFFFFFFF, mx0, 1));
        mx0 = fmaxf(mx0, __shfl_xor_sync(0xFFFFFFFF, mx0, 2));
        mx1 = fmaxf(mx1, __shfl_xor_sync(0xFFFFFFFF, mx1, 1));
        mx1 = fmaxf(mx1, __shfl_xor_sync(0xFFFFFFFF, mx1, 2));

        float c0 = __expf(m0 - mx0);
        float c1 = __expf(m1 - mx1);
        m0 = mx0; m1 = mx1;
        l0 *= c0;  l1 *= c1;
        #pragma unroll
        for (int dt = 0; dt < 8; dt++) {
            o[dt][0] *= c0; o[dt][1] *= c0;
            o[dt][2] *= c1; o[dt][3] *= c1;
        }

        // ---- P = exp(S - m), pack split A-fragments ----
        uint32_t pha[4][4], pla[4][4];
        float rs0 = 0.f, rs1 = 0.f;
        #pragma unroll
        for (int j = 0; j < 8; j++) {
            float p0 = __expf(s[j][0] - m0);
            float p1 = __expf(s[j][1] - m0);
            float p2 = __expf(s[j][2] - m1);
            float p3 = __expf(s[j][3] - m1);
            rs0 += p0 + p1;
            rs1 += p2 + p3;
            uint32_t hi01, lo01, hi23, lo23;
            split_pack(p0, p1, hi01, lo01);
            split_pack(p2, p3, hi23, lo23);
            int c = j >> 1;
            if ((j & 1) == 0) {
                pha[c][0] = hi01; pla[c][0] = lo01;
                pha[c][1] = hi23; pla[c][1] = lo23;
            } else {
                pha[c][2] = hi01; pla[c][2] = lo01;
                pha[c][3] = hi23; pla[c][3] = lo23;
            }
        }
        rs0 += __shfl_xor_sync(0xFFFFFFFF, rs0, 1);
        rs0 += __shfl_xor_sync(0xFFFFFFFF, rs0, 2);
        rs1 += __shfl_xor_sync(0xFFFFFFFF, rs1, 1);
        rs1 += __shfl_xor_sync(0xFFFFFFFF, rs1, 2);
        l0 += rs0;
        l1 += rs1;

        // ---- O += P V: x4 trans loads of row-major V ----
        #pragma unroll
        for (int ks = 0; ks < 4; ks++) {
            #pragma unroll
            for (int dp = 0; dp < 4; dp++) {
                uint32_t vh4[4], vl4[4];
                uint32_t va = st + fb + ks * (16 * ASTRB) + dp * 32;
                ldsm_x4t(vh4, SV_H + va);
                ldsm_x4t(vl4, SV_L + va);
                uint32_t b0h[2] = {vh4[0], vh4[1]}, b1h[2] = {vh4[2], vh4[3]};
                uint32_t b0l[2] = {vl4[0], vl4[1]}, b1l[2] = {vl4[2], vl4[3]};
                mma16816(o[2*dp],   pha[ks], b0h);
                mma16816(o[2*dp],   pha[ks], b0l);
                mma16816(o[2*dp],   pla[ks], b0h);
                mma16816(o[2*dp+1], pha[ks], b1h);
                mma16816(o[2*dp+1], pha[ks], b1l);
                mma16816(o[2*dp+1], pla[ks], b1h);
            }
        }
        __syncthreads();   // all warps done with stage before it's overwritten
    }

    // ---- finalize & write split output ----
    const float i0 = 1.f / l0;
    const float i1 = 1.f / l1;
    const int row0 = q0 + wid * 16 + (lane >> 2);
    const int row1 = row0 + 8;
    const int colb = h * HD + (lane & 3) * 2;
    #pragma unroll
    for (int dt = 0; dt < 8; dt++) {
        int col = colb + dt * 8;
        uint32_t hi0, lo0, hi1, lo1;
        split_pack(o[dt][0] * i0, o[dt][1] * i0, hi0, lo0);
        split_pack(o[dt][2] * i1, o[dt][3] * i1, hi1, lo1);
        size_t g0 = (size_t)(b * TT + row0) * (NH * HD) + col;
        size_t g1 = (size_t)(b * TT + row1) * (NH * HD) + col;
        *(uint32_t*)(Ohg + g0) = hi0;
        *(uint32_t*)(Olg + g0) = lo0;
        *(uint32_t*)(Ohg + g1) = hi1;
        *(uint32_t*)(Olg + g1) = lo1;
    }
}

// ---------------------------------------------------------------------------
// Launch
// ---------------------------------------------------------------------------
extern "C" void kernel_launch(void* const* d_in, const int* in_sizes, int n_in,
                              void* d_out, int out_size)
{
    const float* x    = (const float*)d_in[0];
    const float* cosv = (const float*)d_in[1];
    const float* sinv = (const float*)d_in[2];
    const float* Wq   = (const float*)d_in[3];
    const float* Wk   = (const float*)d_in[4];
    const float* Wv   = (const float*)d_in[5];
    const float* Wo   = (const float*)d_in[6];
    float* out = (float*)d_out;

    float *qkv;
    cudaGetSymbolAddress((void**)&qkv, g_qkv);

    __nv_bfloat16 *xh, *xl, *wqkvh, *wqkvl, *woh, *wol, *ah, *al;
    __nv_bfloat16 *qsh, *qsl, *ksh, *ksl, *vsh, *vsl;
    cudaGetSymbolAddress((void**)&xh,    g_xh);     cudaGetSymbolAddress((void**)&xl,    g_xl);
    cudaGetSymbolAddress((void**)&wqkvh, g_wqkvh);  cudaGetSymbolAddress((void**)&wqkvl, g_wqkvl);
    cudaGetSymbolAddress((void**)&woh,   g_woh);    cudaGetSymbolAddress((void**)&wol,   g_wol);
    cudaGetSymbolAddress((void**)&ah,    g_ah);     cudaGetSymbolAddress((void**)&al,    g_al);
    cudaGetSymbolAddress((void**)&qsh,   g_qsh);    cudaGetSymbolAddress((void**)&qsl,   g_qsl);
    cudaGetSymbolAddress((void**)&ksh,   g_ksh);    cudaGetSymbolAddress((void**)&ksl,   g_ksl);
    cudaGetSymbolAddress((void**)&vsh,   g_vsh);    cudaGetSymbolAddress((void**)&vsl,   g_vsl);

    cudaFuncSetAttribute(gemm_tc, cudaFuncAttributeMaxDynamicSharedMemorySize, GEMM_SMEM);
    cudaFuncSetAttribute(attn_tc, cudaFuncAttributeMaxDynamicSharedMemorySize, ATTN_SMEM);

    // split conversions (inputs + weights; Wq|Wk|Wv concatenated along N)
    {
        int n;
        n = MROWS * DM;     cvt_split<<<(n+255)/256, 256>>>(x,  xh,  xl,  n);
        n = NH*HD * DM;     cvt_split<<<(n+255)/256, 256>>>(Wq, wqkvh, wqkvl, n);
        n = NKV*HD * DM;    cvt_split<<<(n+255)/256, 256>>>(Wk, wqkvh + (size_t)2048*DM, wqkvl + (size_t)2048*DM, n);
        n = NKV*HD * DM;    cvt_split<<<(n+255)/256, 256>>>(Wv, wqkvh + (size_t)2560*DM, wqkvl + (size_t)2560*DM, n);
        n = DM * NH*HD;     cvt_split<<<(n+255)/256, 256>>>(Wo, woh, wol, n);
    }

    // fused Q|K|V projection (N=3072)
    gemm_tc<<<dim3(3072/GBN, MROWS/GBM), 256, GEMM_SMEM>>>(xh, xl, wqkvh, wqkvl, qkv, MROWS, 3072, DM);

    // RoPE fused with split (q pre-scaled by 1/8); v strided split
    {
        int tq = MROWS * NH * 32;
        rope_split<<<(tq + 255)/256, 256>>>(qkv, cosv, sinv, qsh, qsl, MROWS*NH, NH, 3072, 0.125f);
        int tk = MROWS * NKV * 32;
        rope_split<<<(tk + 255)/256, 256>>>(qkv + 2048, cosv, sinv, ksh, ksl, MROWS*NKV, NKV, 3072, 1.0f);
        int nv = MROWS * NKV * HD;
        cvt_splitv<<<(nv + 255)/256, 256>>>(qkv, vsh, vsl, nv);
    }

    // tensor-core flash attention -> split bf16 att
    attn_tc<<<dim3(TT/ATQ, BB*NH), 128, ATTN_SMEM>>>(qsh, qsl, ksh, ksl, vsh, vsl, ah, al);

    // output projection
    gemm_tc<<<dim3(DM/GBN, MROWS/GBM), 256, GEMM_SMEM>>>(ah, al, woh, wol, out, MROWS, DM, DM);
}